// round 14
// baseline (speedup 1.0000x reference)
#include <cuda_runtime.h>
#include <cuda_bf16.h>
#include <math.h>
#include <stdint.h>

#define D_MODEL 1024
#define S_LEN   2048
#define BATCH   2
#define HEADS   16
#define DK      64
#define DFF     4096
#define ROWS    4096
#define D3      3072

#define RM (ROWS * D_MODEL)
#define R3 (ROWS * D3)
#define MM (D_MODEL * D_MODEL)
#define MF (D_MODEL * DFF)
#define RF (ROWS * DFF)

__device__ float g_O [RM];
__device__ float g_X1[RM];
__device__ __nv_bfloat16 g_xh [RM], g_xl [RM];
__device__ __nv_bfloat16 g_qkvh[R3], g_qkvl[R3];
__device__ __nv_bfloat16 g_wqkvh[D_MODEL * D3], g_wqkvl[D_MODEL * D3];
__device__ __nv_bfloat16 g_woh[MM], g_wol[MM];
__device__ __nv_bfloat16 g_W1h[MF], g_W1l[MF];
__device__ __nv_bfloat16 g_W2h[MF], g_W2l[MF];
__device__ __nv_bfloat16 g_aoh[RM], g_aol[RM];
__device__ __nv_bfloat16 g_x1h[RM], g_x1l[RM];
__device__ __nv_bfloat16 g_Hh [RF], g_Hl [RF];

// ---------------- helpers ----------------
__device__ __forceinline__ uint32_t pack_bf16(float a, float b)
{
    __nv_bfloat162 t; t.x = __float2bfloat16(a); t.y = __float2bfloat16(b);
    return *reinterpret_cast<uint32_t*>(&t);
}
__device__ __forceinline__ void mma_16816(float* c, const uint32_t* a, const uint32_t* b)
{
    asm volatile(
        "mma.sync.aligned.m16n8k16.row.col.f32.bf16.bf16.f32 "
        "{%0,%1,%2,%3}, {%4,%5,%6,%7}, {%8,%9}, {%0,%1,%2,%3};\n"
        : "+f"(c[0]), "+f"(c[1]), "+f"(c[2]), "+f"(c[3])
        : "r"(a[0]), "r"(a[1]), "r"(a[2]), "r"(a[3]), "r"(b[0]), "r"(b[1]));
}
__device__ __forceinline__ void cp16(void* d, const void* s)
{
    uint32_t a = (uint32_t)__cvta_generic_to_shared(d);
    asm volatile("cp.async.cg.shared.global [%0], [%1], 16;\n" :: "r"(a), "l"(s));
}
__device__ __forceinline__ void ldsm_x4(uint32_t* r, const void* p)
{
    uint32_t a = (uint32_t)__cvta_generic_to_shared(p);
    asm volatile("ldmatrix.sync.aligned.m8n8.x4.shared.b16 {%0,%1,%2,%3}, [%4];\n"
                 : "=r"(r[0]), "=r"(r[1]), "=r"(r[2]), "=r"(r[3]) : "r"(a));
}
__device__ __forceinline__ void ldsm_x4t(uint32_t* r, const void* p)
{
    uint32_t a = (uint32_t)__cvta_generic_to_shared(p);
    asm volatile("ldmatrix.sync.aligned.m8n8.x4.trans.shared.b16 {%0,%1,%2,%3}, [%4];\n"
                 : "=r"(r[0]), "=r"(r[1]), "=r"(r[2]), "=r"(r[3]) : "r"(a));
}
__device__ __forceinline__ void ldsm_x2(uint32_t* r, const void* p)
{
    uint32_t a = (uint32_t)__cvta_generic_to_shared(p);
    asm volatile("ldmatrix.sync.aligned.m8n8.x2.shared.b16 {%0,%1}, [%2];\n"
                 : "=r"(r[0]), "=r"(r[1]) : "r"(a));
}
__device__ __forceinline__ void ldsm_x2t(uint32_t* r, const void* p)
{
    uint32_t a = (uint32_t)__cvta_generic_to_shared(p);
    asm volatile("ldmatrix.sync.aligned.m8n8.x2.trans.shared.b16 {%0,%1}, [%2];\n"
                 : "=r"(r[0]), "=r"(r[1]) : "r"(a));
}

// ---------------- splits ----------------
__device__ __forceinline__ void split_store(
    __nv_bfloat16* hi, __nv_bfloat16* lo, size_t e, float4 v)
{
    __nv_bfloat16 h0 = __float2bfloat16(v.x), h1 = __float2bfloat16(v.y);
    __nv_bfloat16 h2 = __float2bfloat16(v.z), h3 = __float2bfloat16(v.w);
    __nv_bfloat162 a; a.x = h0; a.y = h1;
    __nv_bfloat162 b; b.x = h2; b.y = h3;
    uint2 hp;
    hp.x = *reinterpret_cast<uint32_t*>(&a);
    hp.y = *reinterpret_cast<uint32_t*>(&b);
    *reinterpret_cast<uint2*>(&hi[e]) = hp;
    uint2 lp;
    lp.x = pack_bf16(v.x - __bfloat162float(h0), v.y - __bfloat162float(h1));
    lp.y = pack_bf16(v.z - __bfloat162float(h2), v.w - __bfloat162float(h3));
    *reinterpret_cast<uint2*>(&lo[e]) = lp;
}

__global__ __launch_bounds__(256) void split4_kernel(
    const float4* __restrict__ x, __nv_bfloat16* __restrict__ hi,
    __nv_bfloat16* __restrict__ lo, int n4)
{
    const int stride = gridDim.x * 256;
    const int i = blockIdx.x * 256 + threadIdx.x;
    float4 v[4];
#pragma unroll
    for (int k = 0; k < 4; k++) {
        int idx = i + k * stride;
        if (idx < n4) v[k] = x[idx];
    }
#pragma unroll
    for (int k = 0; k < 4; k++) {
        int idx = i + k * stride;
        if (idx < n4) split_store(hi, lo, (size_t)idx * 4, v[k]);
    }
}

__global__ __launch_bounds__(256) void split_qkv_kernel(
    const float4* __restrict__ wq, const float4* __restrict__ wk,
    const float4* __restrict__ wv,
    __nv_bfloat16* __restrict__ hi, __nv_bfloat16* __restrict__ lo)
{
    const int which = blockIdx.z;
    const float4* src = (which == 0) ? wq : (which == 1) ? wk : wv;
    int i = blockIdx.x * 256 + threadIdx.x;
    if (i >= MM / 4) return;
    float4 v = src[i];
    int e = i * 4;
    int row = e >> 10, col = e & 1023;
    size_t o = (size_t)row * D3 + which * D_MODEL + col;
    split_store(hi, lo, o, v);
}

// ---------------------------------------------------------------------------
// Fused split-3 bf16 GEMM (best/R10 config, unchanged).
// ---------------------------------------------------------------------------
#define GA_ROW 40
#define GB_ROW 136
#define A_BYTES (128 * GA_ROW * 2)
#define B_BYTES (32 * GB_ROW * 2)
#define STAGE_BYTES (2 * A_BYTES + 2 * B_BYTES)
#define GSMEM_TOTAL (3 * STAGE_BYTES)

template <bool BIAS, bool RELU, bool SPLIT>
__global__ __launch_bounds__(256, 2) void hgemm_fused(
    const __nv_bfloat16* __restrict__ Ah_, const __nv_bfloat16* __restrict__ Al_,
    const __nv_bfloat16* __restrict__ Bh_, const __nv_bfloat16* __restrict__ Bl_,
    const float* __restrict__ bias, float* __restrict__ C,
    __nv_bfloat16* __restrict__ Ch, __nv_bfloat16* __restrict__ Cl,
    int M, int N, int K)
{
    extern __shared__ __align__(16) char gsm[];
    auto As = [&](int hl, int s) {
        return (__nv_bfloat16*)(gsm + s * STAGE_BYTES + hl * A_BYTES);
    };
    auto Bs = [&](int hl, int s) {
        return (__nv_bfloat16*)(gsm + s * STAGE_BYTES + 2 * A_BYTES + hl * B_BYTES);
    };

    const int tid  = threadIdx.x;
    const int lane = tid & 31;
    const int warp = tid >> 5;
    const int wm   = warp & 3;
    const int wn   = warp >> 2;
    const int rowBase = blockIdx.y * 128;
    const int colBase = blockIdx.x * 128;
    const int nc = K / 32;

    float acc[2][8][4];
#pragma unroll
    for (int i = 0; i < 2; i++)
#pragma unroll
        for (int j = 0; j < 8; j++)
#pragma unroll
            for (int k = 0; k < 4; k++) acc[i][j][k] = 0.f;

    auto issue = [&](int c) {
        int s = c % 3, k0 = c * 32;
#pragma unroll
        for (int i = 0; i < 2; i++) {
            int t = tid * 2 + i;
            int r = t >> 2, c8 = (t & 3) * 8;
            const size_t g = (size_t)(rowBase + r) * K + k0 + c8;
            cp16(As(0, s) + r * GA_ROW + c8, Ah_ + g);
            cp16(As(1, s) + r * GA_ROW + c8, Al_ + g);
        }
#pragma unroll
        for (int i = 0; i < 2; i++) {
            int t = tid + i * 256;
            int r = t >> 4, c8 = (t & 15) * 8;
            const size_t g = (size_t)(k0 + r) * N + colBase + c8;
            cp16(Bs(0, s) + r * GB_ROW + c8, Bh_ + g);
            cp16(Bs(1, s) + r * GB_ROW + c8, Bl_ + g);
        }
        asm volatile("cp.async.commit_group;\n" ::: "memory");
    };

    issue(0);
    issue(1);
    for (int c = 0; c < nc; c++) {
        const int s = c % 3;
        if (c + 2 < nc) {
            asm volatile("cp.async.wait_group 1;\n" ::: "memory");
        } else {
            asm volatile("cp.async.wait_group 0;\n" ::: "memory");
        }
        __syncthreads();
        if (c + 2 < nc) issue(c + 2);

#pragma unroll
        for (int ks = 0; ks < 32; ks += 16) {
            uint32_t ahf[2][4], alf[2][4];
#pragma unroll
            for (int fm = 0; fm < 2; fm++) {
                int row = wm * 32 + fm * 16 + (lane & 15);
                int col = ks + ((lane >> 4) << 3);
                ldsm_x4(ahf[fm], As(0, s) + row * GA_ROW + col);
                ldsm_x4(alf[fm], As(1, s) + row * GA_ROW + col);
            }
            const int brow = ks + (lane & 7) + ((lane >> 3) & 1) * 8;
            const int bcof = (lane >> 4) * 8;
#pragma unroll
            for (int fnp = 0; fnp < 4; fnp++) {
                const int bcol = wn * 64 + fnp * 16 + bcof;
                uint32_t bh4[4];
                ldsm_x4t(bh4, Bs(0, s) + brow * GB_ROW + bcol);
#pragma unroll
                for (int fm = 0; fm < 2; fm++) {
                    mma_16816(acc[fm][2 * fnp],     ahf[fm], bh4 + 0);
                    mma_16816(acc[fm][2 * fnp + 1], ahf[fm], bh4 + 2);
                }
#pragma unroll
                for (int fm = 0; fm < 2; fm++) {
                    mma_16816(acc[fm][2 * fnp],     alf[fm], bh4 + 0);
                    mma_16816(acc[fm][2 * fnp + 1], alf[fm], bh4 + 2);
                }
                uint32_t bl4[4];
                ldsm_x4t(bl4, Bs(1, s) + brow * GB_ROW + bcol);
#pragma unroll
                for (int fm = 0; fm < 2; fm++) {
                    mma_16816(acc[fm][2 * fnp],     ahf[fm], bl4 + 0);
                    mma_16816(acc[fm][2 * fnp + 1], ahf[fm], bl4 + 2);
                }
            }
        }
        __syncthreads();
    }

#pragma unroll
    for (int fm = 0; fm < 2; fm++) {
#pragma unroll
        for (int fn = 0; fn < 8; fn++) {
            int r0 = rowBase + wm * 32 + fm * 16 + (lane >> 2);
            int c0 = colBase + wn * 64 + fn * 8 + (lane & 3) * 2;
            float bx = 0.f, by = 0.f;
            if (BIAS) { bx = bias[c0]; by = bias[c0 + 1]; }
#pragma unroll
            for (int hh = 0; hh < 2; hh++) {
                int r = r0 + hh * 8;
                float v0 = acc[fm][fn][hh * 2 + 0] + bx;
                float v1 = acc[fm][fn][hh * 2 + 1] + by;
                if (RELU) { v0 = fmaxf(v0, 0.f); v1 = fmaxf(v1, 0.f); }
                size_t idx = (size_t)r * N + c0;
                if (SPLIT) {
                    __nv_bfloat16 h0 = __float2bfloat16(v0);
                    __nv_bfloat16 h1 = __float2bfloat16(v1);
                    __nv_bfloat162 hp; hp.x = h0; hp.y = h1;
                    *reinterpret_cast<__nv_bfloat162*>(&Ch[idx]) = hp;
                    __nv_bfloat162 lp;
                    lp.x = __float2bfloat16(v0 - __bfloat162float(h0));
                    lp.y = __float2bfloat16(v1 - __bfloat162float(h1));
                    *reinterpret_cast<__nv_bfloat162*>(&Cl[idx]) = lp;
                } else {
                    *reinterpret_cast<float2*>(&C[idx]) = make_float2(v0, v1);
                }
            }
        }
    }
}

// ---------------------------------------------------------------------------
// Attention: Br=128 (8 warps, 256 threads, 2 CTAs/SM), Bc=64, split-3.
// Q staging ALIASES the K/V tile region (Q smem is dead after frag load).
// ---------------------------------------------------------------------------
#define APAD 72
#define ATILE (64 * APAD)                          // halves per 64-row tile
#define ATT_SMEM_BYTES (4 * ATILE * 2 + 64 * 4)    // 4 K/V tiles + mask

__global__ __launch_bounds__(256, 2) void attn_mma(
    const __nv_bfloat16* __restrict__ Qh, const __nv_bfloat16* __restrict__ Ql,
    const __nv_bfloat16* __restrict__ Kh, const __nv_bfloat16* __restrict__ Kl,
    const __nv_bfloat16* __restrict__ Vh, const __nv_bfloat16* __restrict__ Vl,
    const int* __restrict__ mask,
    __nv_bfloat16* __restrict__ Oh, __nv_bfloat16* __restrict__ Ol, int ldin)
{
    extern __shared__ __align__(16) __nv_bfloat16 smb[];
    // K/V layout (main loop):
    __nv_bfloat16* sKh = smb;
    __nv_bfloat16* sKl = smb + ATILE;
    __nv_bfloat16* sVh = smb + 2 * ATILE;
    __nv_bfloat16* sVl = smb + 3 * ATILE;
    // Q staging aliases [0, 4*ATILE): sQh 128 rows then sQl 128 rows
    __nv_bfloat16* sQh = smb;
    __nv_bfloat16* sQl = smb + 2 * ATILE;
    int* Ms = (int*)(smb + 4 * ATILE);

    const int qt = blockIdx.x, h = blockIdx.y, b = blockIdx.z;
    const int tid = threadIdx.x, lane = tid & 31, warp = tid >> 5, l16 = lane & 15;
    const size_t rowbase = (size_t)b * S_LEN + qt * 128;
    const int ch = h * DK;

    // Stage Q (128 rows x 64 cols, hi+lo) into aliased region
    for (int i = tid; i < 1024; i += 256) {
        int r = i >> 3, c8 = (i & 7) * 8;
        size_t g = (rowbase + r) * (size_t)ldin + ch + c8;
        cp16(&sQh[r * APAD + c8], Qh + g);
        cp16(&sQl[r * APAD + c8], Ql + g);
    }
    asm volatile("cp.async.commit_group;\n" ::: "memory");
    asm volatile("cp.async.wait_group 0;\n" ::: "memory");
    __syncthreads();

    uint32_t qfh[4][4], qfl[4][4];
#pragma unroll
    for (int kc = 0; kc < 4; kc++) {
        int row = warp * 16 + l16, col = kc * 16 + (lane >> 4) * 8;
        ldsm_x4(qfh[kc], &sQh[row * APAD + col]);
        ldsm_x4(qfl[kc], &sQl[row * APAD + col]);
    }

    float m0 = -1e30f, m1 = -1e30f, l0 = 0.f, l1 = 0.f;
    float o[8][4];
#pragma unroll
    for (int nf = 0; nf < 8; nf++)
#pragma unroll
        for (int j = 0; j < 4; j++) o[nf][j] = 0.f;

    for (int kt = 0; kt < S_LEN / 64; kt++) {
        __syncthreads();   // all warps done with previous tiles (or Q frags)
        for (int i = tid; i < 512; i += 256) {
            int r = i >> 3, c8 = (i & 7) * 8;
            size_t g = ((size_t)b * S_LEN + kt * 64 + r) * (size_t)ldin + ch + c8;
            int so = r * APAD + c8;
            cp16(&sKh[so], Kh + g);
            cp16(&sKl[so], Kl + g);
            cp16(&sVh[so], Vh + g);
            cp16(&sVl[so], Vl + g);
        }
        if (tid < 64) Ms[tid] = mask[(size_t)b * S_LEN + kt * 64 + tid];
        asm volatile("cp.async.commit_group;\n" ::: "memory");
        asm volatile("cp.async.wait_group 0;\n" ::: "memory");
        __syncthreads();

        float s[8][4];
#pragma unroll
        for (int nf = 0; nf < 8; nf++)
#pragma unroll
            for (int j = 0; j < 4; j++) s[nf][j] = 0.f;

#pragma unroll
        for (int kc = 0; kc < 4; kc++) {
            int rr = (l16 & 7), cc = kc * 16 + (l16 >> 3) * 8;
#pragma unroll
            for (int nf = 0; nf < 8; nf++) {
                uint32_t bh[2];
                ldsm_x2(bh, &sKh[(nf * 8 + rr) * APAD + cc]);
                mma_16816(s[nf], qfh[kc], bh);
                mma_16816(s[nf], qfl[kc], bh);
            }
#pragma unroll
            for (int nf = 0; nf < 8; nf++) {
                uint32_t bl[2];
                ldsm_x2(bl, &sKl[(nf * 8 + rr) * APAD + cc]);
                mma_16816(s[nf], qfh[kc], bl);
            }
        }

#pragma unroll
        for (int nf = 0; nf < 8; nf++) {
            int c0 = nf * 8 + (lane & 3) * 2;
            bool z0 = (Ms[c0] == 0), z1 = (Ms[c0 + 1] == 0);
            s[nf][0] = z0 ? -1e9f : s[nf][0] * 0.125f;
            s[nf][1] = z1 ? -1e9f : s[nf][1] * 0.125f;
            s[nf][2] = z0 ? -1e9f : s[nf][2] * 0.125f;
            s[nf][3] = z1 ? -1e9f : s[nf][3] * 0.125f;
        }

        float tm0 = -1e30f, tm1 = -1e30f;
#pragma unroll
        for (int nf = 0; nf < 8; nf++) {
            tm0 = fmaxf(tm0, fmaxf(s[nf][0], s[nf][1]));
            tm1 = fmaxf(tm1, fmaxf(s[nf][2], s[nf][3]));
        }
        tm0 = fmaxf(tm0, __shfl_xor_sync(0xffffffffu, tm0, 1));
        tm0 = fmaxf(tm0, __shfl_xor_sync(0xffffffffu, tm0, 2));
        tm1 = fmaxf(tm1, __shfl_xor_sync(0xffffffffu, tm1, 1));
        tm1 = fmaxf(tm1, __shfl_xor_sync(0xffffffffu, tm1, 2));

        float mn0 = fmaxf(m0, tm0), mn1 = fmaxf(m1, tm1);
        float sc0 = __expf(m0 - mn0), sc1 = __expf(m1 - mn1);
        m0 = mn0; m1 = mn1;

        float ts0 = 0.f, ts1 = 0.f;
#pragma unroll
        for (int nf = 0; nf < 8; nf++) {
            s[nf][0] = __expf(s[nf][0] - m0);
            s[nf][1] = __expf(s[nf][1] - m0);
            s[nf][2] = __expf(s[nf][2] - m1);
            s[nf][3] = __expf(s[nf][3] - m1);
            ts0 += s[nf][0] + s[nf][1];
            ts1 += s[nf][2] + s[nf][3];
        }
        ts0 += __shfl_xor_sync(0xffffffffu, ts0, 1);
        ts0 += __shfl_xor_sync(0xffffffffu, ts0, 2);
        ts1 += __shfl_xor_sync(0xffffffffu, ts1, 1);
        ts1 += __shfl_xor_sync(0xffffffffu, ts1, 2);
        l0 = l0 * sc0 + ts0;
        l1 = l1 * sc1 + ts1;

#pragma unroll
        for (int nf = 0; nf < 8; nf++) {
            o[nf][0] *= sc0; o[nf][1] *= sc0;
            o[nf][2] *= sc1; o[nf][3] *= sc1;
        }

#pragma unroll
        for (int j = 0; j < 4; j++) {
            uint32_t ah[4], al[4];
#pragma unroll
            for (int half = 0; half < 2; half++) {
                const float* p = s[2 * j + half];
#pragma unroll
                for (int rr2 = 0; rr2 < 2; rr2++) {
                    float p0 = p[rr2 * 2 + 0], p1 = p[rr2 * 2 + 1];
                    __nv_bfloat16 h0 = __float2bfloat16(p0), h1 = __float2bfloat16(p1);
                    __nv_bfloat162 hp; hp.x = h0; hp.y = h1;
                    ah[half * 2 + rr2] = *reinterpret_cast<uint32_t*>(&hp);
                    al[half * 2 + rr2] = pack_bf16(p0 - __bfloat162float(h0),
                                                   p1 - __bfloat162float(h1));
                }
            }
            int vrow = j * 16 + l16;
#pragma unroll
            for (int nf = 0; nf < 8; nf++) {
                uint32_t bvh[2];
                ldsm_x2t(bvh, &sVh[vrow * APAD + nf * 8]);
                mma_16816(o[nf], ah, bvh);
                mma_16816(o[nf], al, bvh);
            }
#pragma unroll
            for (int nf = 0; nf < 8; nf++) {
                uint32_t bvl[2];
                ldsm_x2t(bvl, &sVl[vrow * APAD + nf * 8]);
                mma_16816(o[nf], ah, bvl);
            }
        }
    }

    float inv0 = 1.f / l0, inv1 = 1.f / l1;
    int r0 = warp * 16 + (lane >> 2);
#pragma unroll
    for (int nf = 0; nf < 8; nf++) {
        int c0 = ch + nf * 8 + (lane & 3) * 2;
#pragma unroll
        for (int hh = 0; hh < 2; hh++) {
            float v0 = o[nf][hh * 2 + 0] * (hh ? inv1 : inv0);
            float v1 = o[nf][hh * 2 + 1] * (hh ? inv1 : inv0);
            size_t idx = (rowbase + r0 + hh * 8) * D_MODEL + c0;
            __nv_bfloat16 h0 = __float2bfloat16(v0), h1 = __float2bfloat16(v1);
            __nv_bfloat162 hp; hp.x = h0; hp.y = h1;
            *reinterpret_cast<__nv_bfloat162*>(&Oh[idx]) = hp;
            __nv_bfloat162 lp;
            lp.x = __float2bfloat16(v0 - __bfloat162float(h0));
            lp.y = __float2bfloat16(v1 - __bfloat162float(h1));
            *reinterpret_cast<__nv_bfloat162*>(&Ol[idx]) = lp;
        }
    }
}

// ---------------- residual + LayerNorm ----------------
template <bool SPLITOUT>
__global__ __launch_bounds__(256) void add_ln_kernel(
    const float* __restrict__ A, const float* __restrict__ Bp,
    const float* __restrict__ alpha, const float* __restrict__ beta,
    float* __restrict__ out, __nv_bfloat16* __restrict__ oh,
    __nv_bfloat16* __restrict__ ol)
{
    __shared__ float buf[D_MODEL];
    __shared__ float red_s[8], red_q[8];
    __shared__ float sh_mean, sh_inv;
    const int row = blockIdx.x, tid = threadIdx.x;
    const size_t base = (size_t)row * D_MODEL;

    float s = 0.f, q = 0.f;
    for (int c = tid; c < D_MODEL; c += 256) {
        float v = A[base + c] + Bp[base + c];
        buf[c] = v; s += v; q = fmaf(v, v, q);
    }
#pragma unroll
    for (int msk = 16; msk >= 1; msk >>= 1) {
        s += __shfl_xor_sync(0xffffffffu, s, msk);
        q += __shfl_xor_sync(0xffffffffu, q, msk);
    }
    if ((tid & 31) == 0) { red_s[tid >> 5] = s; red_q[tid >> 5] = q; }
    __syncthreads();
    if (tid == 0) {
        float S = 0.f, Q = 0.f;
#pragma unroll
        for (int i = 0; i < 8; i++) { S += red_s[i]; Q += red_q[i]; }
        float mean = S * (1.f / (float)D_MODEL);
        float var = fmaxf((Q - (float)D_MODEL * mean * mean) *
                          (1.f / (float)(D_MODEL - 1)), 0.f);
        sh_mean = mean;
        sh_inv = 1.f / (sqrtf(var) + 1e-6f);
    }
    __syncthreads();
    const float mean = sh_mean, inv = sh_inv;
    for (int c = tid; c < D_MODEL; c += 256) {
        float v = fmaf(alpha[c], (buf[c] - mean) * inv, beta[c]);
        out[base + c] = v;
        if (SPLITOUT) {
            __nv_bfloat16 hv = __float2bfloat16(v);
            oh[base + c] = hv;
            ol[base + c] = __float2bfloat16(v - __bfloat162float(hv));
        }
    }
}

// ---------------- launch ----------------
extern "C" void kernel_launch(void* const* d_in, const int* in_sizes, int n_in,
                              void* d_out, int out_size)
{
    const float* x   = (const float*)d_in[0];
    const int* mask  = (const int*)d_in[1];
    const float* w_q = (const float*)d_in[2];
    const float* w_k = (const float*)d_in[3];
    const float* w_v = (const float*)d_in[4];
    const float* w_o = (const float*)d_in[5];
    const float* W1  = (const float*)d_in[6];
    const float* b1  = (const float*)d_in[7];
    const float* W2  = (const float*)d_in[8];
    const float* b2  = (const float*)d_in[9];
    const float* a1  = (const float*)d_in[10];
    const float* be1 = (const float*)d_in[11];
    const float* a2  = (const float*)d_in[12];
    const float* be2 = (const float*)d_in[13];
    float* out = (float*)d_out;

    float *O, *X1;
    cudaGetSymbolAddress((void**)&O, g_O);
    cudaGetSymbolAddress((void**)&X1, g_X1);
    __nv_bfloat16 *xh, *xl, *qkvh, *qkvl, *wqkvh, *wqkvl, *woh, *wol;
    __nv_bfloat16 *W1h, *W1l, *W2h, *W2l, *aoh, *aol, *x1h, *x1l, *Hh, *Hl;
    cudaGetSymbolAddress((void**)&xh, g_xh);       cudaGetSymbolAddress((void**)&xl, g_xl);
    cudaGetSymbolAddress((void**)&qkvh, g_qkvh);   cudaGetSymbolAddress((void**)&qkvl, g_qkvl);
    cudaGetSymbolAddress((void**)&wqkvh, g_wqkvh); cudaGetSymbolAddress((void**)&wqkvl, g_wqkvl);
    cudaGetSymbolAddress((void**)&woh, g_woh);     cudaGetSymbolAddress((void**)&wol, g_wol);
    cudaGetSymbolAddress((void**)&W1h, g_W1h);     cudaGetSymbolAddress((void**)&W1l, g_W1l);
    cudaGetSymbolAddress((void**)&W2h, g_W2h);     cudaGetSymbolAddress((void**)&W2l, g_W2l);
    cudaGetSymbolAddress((void**)&aoh, g_aoh);     cudaGetSymbolAddress((void**)&aol, g_aol);
    cudaGetSymbolAddress((void**)&x1h, g_x1h);     cudaGetSymbolAddress((void**)&x1l, g_x1l);
    cudaGetSymbolAddress((void**)&Hh, g_Hh);       cudaGetSymbolAddress((void**)&Hl, g_Hl);

    cudaFuncSetAttribute(attn_mma, cudaFuncAttributeMaxDynamicSharedMemorySize,
                         ATT_SMEM_BYTES);
    cudaFuncSetAttribute(hgemm_fused<false, false, true>,
                         cudaFuncAttributeMaxDynamicSharedMemorySize, GSMEM_TOTAL);
    cudaFuncSetAttribute(hgemm_fused<false, false, false>,
                         cudaFuncAttributeMaxDynamicSharedMemorySize, GSMEM_TOTAL);
    cudaFuncSetAttribute(hgemm_fused<true, true, true>,
                         cudaFuncAttributeMaxDynamicSharedMemorySize, GSMEM_TOTAL);
    cudaFuncSetAttribute(hgemm_fused<true, false, false>,
                         cudaFuncAttributeMaxDynamicSharedMemorySize, GSMEM_TOTAL);

    const dim3 blk(256);
    const dim3 gQKV(D3 / 128, ROWS / 128);
    const dim3 gP(D_MODEL / 128, ROWS / 128);
    const dim3 gF(DFF / 128, ROWS / 128);

    // 1: split x; 2: qkv weight split; 3: QKV GEMM; 4: attention (profiled)
    split4_kernel<<<RM / 4096, blk>>>((const float4*)x, xh, xl, RM / 4);
    split_qkv_kernel<<<dim3(MM / 1024, 1, 3), blk>>>(
        (const float4*)w_q, (const float4*)w_k, (const float4*)w_v, wqkvh, wqkvl);

    hgemm_fused<false, false, true><<<gQKV, blk, GSMEM_TOTAL>>>(
        xh, xl, wqkvh, wqkvl, nullptr, nullptr, qkvh, qkvl, ROWS, D3, D_MODEL);

    attn_mma<<<dim3(S_LEN / 128, HEADS, BATCH), 256, ATT_SMEM_BYTES>>>(
        qkvh, qkvl, qkvh + D_MODEL, qkvl + D_MODEL,
        qkvh + 2 * D_MODEL, qkvl + 2 * D_MODEL, mask, aoh, aol, D3);

    split4_kernel<<<MM / 4096, blk>>>((const float4*)w_o, woh, wol, MM / 4);
    split4_kernel<<<MF / 4096, blk>>>((const float4*)W1, W1h, W1l, MF / 4);
    split4_kernel<<<MF / 4096, blk>>>((const float4*)W2, W2h, W2l, MF / 4);

    hgemm_fused<false, false, false><<<gP, blk, GSMEM_TOTAL>>>(
        aoh, aol, woh, wol, nullptr, O, nullptr, nullptr, ROWS, D_MODEL, D_MODEL);

    add_ln_kernel<true><<<ROWS, blk>>>(x, O, a1, be1, X1, x1h, x1l);

    hgemm_fused<true, true, true><<<gF, blk, GSMEM_TOTAL>>>(
        x1h, x1l, W1h, W1l, b1, nullptr, Hh, Hl, ROWS, DFF, D_MODEL);

    hgemm_fused<true, false, false><<<gP, blk, GSMEM_TOTAL>>>(
        Hh, Hl, W2h, W2l, b2, O, nullptr, nullptr, ROWS, D_MODEL, DFF);

    add_ln_kernel<false><<<ROWS, blk>>>(X1, O, a2, be2, out, nullptr, nullptr);
}

// round 15
// speedup vs baseline: 1.0085x; 1.0085x over previous
#include <cuda_runtime.h>
#include <cuda_bf16.h>
#include <math.h>
#include <stdint.h>

#define D_MODEL 1024
#define S_LEN   2048
#define BATCH   2
#define HEADS   16
#define DK      64
#define DFF     4096
#define ROWS    4096
#define D3      3072

#define RM (ROWS * D_MODEL)
#define R3 (ROWS * D3)
#define MM (D_MODEL * D_MODEL)
#define MF (D_MODEL * DFF)
#define RF (ROWS * DFF)

__device__ float g_O [RM];
__device__ float g_X1[RM];
__device__ __nv_bfloat16 g_xh [RM], g_xl [RM];
__device__ __nv_bfloat16 g_qkvh[R3], g_qkvl[R3];
__device__ __nv_bfloat16 g_wqkvh[D_MODEL * D3], g_wqkvl[D_MODEL * D3];
__device__ __nv_bfloat16 g_woh[MM], g_wol[MM];
__device__ __nv_bfloat16 g_W1h[MF], g_W1l[MF];
__device__ __nv_bfloat16 g_W2h[MF], g_W2l[MF];
__device__ __nv_bfloat16 g_aoh[RM], g_aol[RM];
__device__ __nv_bfloat16 g_x1h[RM], g_x1l[RM];
__device__ __nv_bfloat16 g_Hh [RF], g_Hl [RF];

// ---------------- helpers ----------------
__device__ __forceinline__ uint32_t pack_bf16(float a, float b)
{
    __nv_bfloat162 t; t.x = __float2bfloat16(a); t.y = __float2bfloat16(b);
    return *reinterpret_cast<uint32_t*>(&t);
}
__device__ __forceinline__ void mma_16816(float* c, const uint32_t* a, const uint32_t* b)
{
    asm volatile(
        "mma.sync.aligned.m16n8k16.row.col.f32.bf16.bf16.f32 "
        "{%0,%1,%2,%3}, {%4,%5,%6,%7}, {%8,%9}, {%0,%1,%2,%3};\n"
        : "+f"(c[0]), "+f"(c[1]), "+f"(c[2]), "+f"(c[3])
        : "r"(a[0]), "r"(a[1]), "r"(a[2]), "r"(a[3]), "r"(b[0]), "r"(b[1]));
}
__device__ __forceinline__ void cp16(void* d, const void* s)
{
    uint32_t a = (uint32_t)__cvta_generic_to_shared(d);
    asm volatile("cp.async.cg.shared.global [%0], [%1], 16;\n" :: "r"(a), "l"(s));
}
__device__ __forceinline__ void ldsm_x4(uint32_t* r, const void* p)
{
    uint32_t a = (uint32_t)__cvta_generic_to_shared(p);
    asm volatile("ldmatrix.sync.aligned.m8n8.x4.shared.b16 {%0,%1,%2,%3}, [%4];\n"
                 : "=r"(r[0]), "=r"(r[1]), "=r"(r[2]), "=r"(r[3]) : "r"(a));
}
__device__ __forceinline__ void ldsm_x4t(uint32_t* r, const void* p)
{
    uint32_t a = (uint32_t)__cvta_generic_to_shared(p);
    asm volatile("ldmatrix.sync.aligned.m8n8.x4.trans.shared.b16 {%0,%1,%2,%3}, [%4];\n"
                 : "=r"(r[0]), "=r"(r[1]), "=r"(r[2]), "=r"(r[3]) : "r"(a));
}
__device__ __forceinline__ void ldsm_x2(uint32_t* r, const void* p)
{
    uint32_t a = (uint32_t)__cvta_generic_to_shared(p);
    asm volatile("ldmatrix.sync.aligned.m8n8.x2.shared.b16 {%0,%1}, [%2];\n"
                 : "=r"(r[0]), "=r"(r[1]) : "r"(a));
}
__device__ __forceinline__ void ldsm_x2t(uint32_t* r, const void* p)
{
    uint32_t a = (uint32_t)__cvta_generic_to_shared(p);
    asm volatile("ldmatrix.sync.aligned.m8n8.x2.trans.shared.b16 {%0,%1}, [%2];\n"
                 : "=r"(r[0]), "=r"(r[1]) : "r"(a));
}

// ---------------- splits ----------------
__device__ __forceinline__ void split_store(
    __nv_bfloat16* hi, __nv_bfloat16* lo, size_t e, float4 v)
{
    __nv_bfloat16 h0 = __float2bfloat16(v.x), h1 = __float2bfloat16(v.y);
    __nv_bfloat16 h2 = __float2bfloat16(v.z), h3 = __float2bfloat16(v.w);
    __nv_bfloat162 a; a.x = h0; a.y = h1;
    __nv_bfloat162 b; b.x = h2; b.y = h3;
    uint2 hp;
    hp.x = *reinterpret_cast<uint32_t*>(&a);
    hp.y = *reinterpret_cast<uint32_t*>(&b);
    *reinterpret_cast<uint2*>(&hi[e]) = hp;
    uint2 lp;
    lp.x = pack_bf16(v.x - __bfloat162float(h0), v.y - __bfloat162float(h1));
    lp.y = pack_bf16(v.z - __bfloat162float(h2), v.w - __bfloat162float(h3));
    *reinterpret_cast<uint2*>(&lo[e]) = lp;
}

__global__ __launch_bounds__(256) void split4_kernel(
    const float4* __restrict__ x, __nv_bfloat16* __restrict__ hi,
    __nv_bfloat16* __restrict__ lo, int n4)
{
    const int stride = gridDim.x * 256;
    const int i = blockIdx.x * 256 + threadIdx.x;
    float4 v[4];
#pragma unroll
    for (int k = 0; k < 4; k++) {
        int idx = i + k * stride;
        if (idx < n4) v[k] = x[idx];
    }
#pragma unroll
    for (int k = 0; k < 4; k++) {
        int idx = i + k * stride;
        if (idx < n4) split_store(hi, lo, (size_t)idx * 4, v[k]);
    }
}

__global__ __launch_bounds__(256) void split_qkv_kernel(
    const float4* __restrict__ wq, const float4* __restrict__ wk,
    const float4* __restrict__ wv,
    __nv_bfloat16* __restrict__ hi, __nv_bfloat16* __restrict__ lo)
{
    const int which = blockIdx.z;
    const float4* src = (which == 0) ? wq : (which == 1) ? wk : wv;
    int i = blockIdx.x * 256 + threadIdx.x;
    if (i >= MM / 4) return;
    float4 v = src[i];
    int e = i * 4;
    int row = e >> 10, col = e & 1023;
    size_t o = (size_t)row * D3 + which * D_MODEL + col;
    split_store(hi, lo, o, v);
}

// ---------------------------------------------------------------------------
// Fused split-3 bf16 GEMM (best/R10 config, unchanged).
// ---------------------------------------------------------------------------
#define GA_ROW 40
#define GB_ROW 136
#define A_BYTES (128 * GA_ROW * 2)
#define B_BYTES (32 * GB_ROW * 2)
#define STAGE_BYTES (2 * A_BYTES + 2 * B_BYTES)
#define GSMEM_TOTAL (3 * STAGE_BYTES)

template <bool BIAS, bool RELU, bool SPLIT>
__global__ __launch_bounds__(256, 2) void hgemm_fused(
    const __nv_bfloat16* __restrict__ Ah_, const __nv_bfloat16* __restrict__ Al_,
    const __nv_bfloat16* __restrict__ Bh_, const __nv_bfloat16* __restrict__ Bl_,
    const float* __restrict__ bias, float* __restrict__ C,
    __nv_bfloat16* __restrict__ Ch, __nv_bfloat16* __restrict__ Cl,
    int M, int N, int K)
{
    extern __shared__ __align__(16) char gsm[];
    auto As = [&](int hl, int s) {
        return (__nv_bfloat16*)(gsm + s * STAGE_BYTES + hl * A_BYTES);
    };
    auto Bs = [&](int hl, int s) {
        return (__nv_bfloat16*)(gsm + s * STAGE_BYTES + 2 * A_BYTES + hl * B_BYTES);
    };

    const int tid  = threadIdx.x;
    const int lane = tid & 31;
    const int warp = tid >> 5;
    const int wm   = warp & 3;
    const int wn   = warp >> 2;
    const int rowBase = blockIdx.y * 128;
    const int colBase = blockIdx.x * 128;
    const int nc = K / 32;

    float acc[2][8][4];
#pragma unroll
    for (int i = 0; i < 2; i++)
#pragma unroll
        for (int j = 0; j < 8; j++)
#pragma unroll
            for (int k = 0; k < 4; k++) acc[i][j][k] = 0.f;

    auto issue = [&](int c) {
        int s = c % 3, k0 = c * 32;
#pragma unroll
        for (int i = 0; i < 2; i++) {
            int t = tid * 2 + i;
            int r = t >> 2, c8 = (t & 3) * 8;
            const size_t g = (size_t)(rowBase + r) * K + k0 + c8;
            cp16(As(0, s) + r * GA_ROW + c8, Ah_ + g);
            cp16(As(1, s) + r * GA_ROW + c8, Al_ + g);
        }
#pragma unroll
        for (int i = 0; i < 2; i++) {
            int t = tid + i * 256;
            int r = t >> 4, c8 = (t & 15) * 8;
            const size_t g = (size_t)(k0 + r) * N + colBase + c8;
            cp16(Bs(0, s) + r * GB_ROW + c8, Bh_ + g);
            cp16(Bs(1, s) + r * GB_ROW + c8, Bl_ + g);
        }
        asm volatile("cp.async.commit_group;\n" ::: "memory");
    };

    issue(0);
    issue(1);
    for (int c = 0; c < nc; c++) {
        const int s = c % 3;
        if (c + 2 < nc) {
            asm volatile("cp.async.wait_group 1;\n" ::: "memory");
        } else {
            asm volatile("cp.async.wait_group 0;\n" ::: "memory");
        }
        __syncthreads();
        if (c + 2 < nc) issue(c + 2);

#pragma unroll
        for (int ks = 0; ks < 32; ks += 16) {
            uint32_t ahf[2][4], alf[2][4];
#pragma unroll
            for (int fm = 0; fm < 2; fm++) {
                int row = wm * 32 + fm * 16 + (lane & 15);
                int col = ks + ((lane >> 4) << 3);
                ldsm_x4(ahf[fm], As(0, s) + row * GA_ROW + col);
                ldsm_x4(alf[fm], As(1, s) + row * GA_ROW + col);
            }
            const int brow = ks + (lane & 7) + ((lane >> 3) & 1) * 8;
            const int bcof = (lane >> 4) * 8;
#pragma unroll
            for (int fnp = 0; fnp < 4; fnp++) {
                const int bcol = wn * 64 + fnp * 16 + bcof;
                uint32_t bh4[4];
                ldsm_x4t(bh4, Bs(0, s) + brow * GB_ROW + bcol);
#pragma unroll
                for (int fm = 0; fm < 2; fm++) {
                    mma_16816(acc[fm][2 * fnp],     ahf[fm], bh4 + 0);
                    mma_16816(acc[fm][2 * fnp + 1], ahf[fm], bh4 + 2);
                }
#pragma unroll
                for (int fm = 0; fm < 2; fm++) {
                    mma_16816(acc[fm][2 * fnp],     alf[fm], bh4 + 0);
                    mma_16816(acc[fm][2 * fnp + 1], alf[fm], bh4 + 2);
                }
                uint32_t bl4[4];
                ldsm_x4t(bl4, Bs(1, s) + brow * GB_ROW + bcol);
#pragma unroll
                for (int fm = 0; fm < 2; fm++) {
                    mma_16816(acc[fm][2 * fnp],     ahf[fm], bl4 + 0);
                    mma_16816(acc[fm][2 * fnp + 1], ahf[fm], bl4 + 2);
                }
            }
        }
        __syncthreads();
    }

#pragma unroll
    for (int fm = 0; fm < 2; fm++) {
#pragma unroll
        for (int fn = 0; fn < 8; fn++) {
            int r0 = rowBase + wm * 32 + fm * 16 + (lane >> 2);
            int c0 = colBase + wn * 64 + fn * 8 + (lane & 3) * 2;
            float bx = 0.f, by = 0.f;
            if (BIAS) { bx = bias[c0]; by = bias[c0 + 1]; }
#pragma unroll
            for (int hh = 0; hh < 2; hh++) {
                int r = r0 + hh * 8;
                float v0 = acc[fm][fn][hh * 2 + 0] + bx;
                float v1 = acc[fm][fn][hh * 2 + 1] + by;
                if (RELU) { v0 = fmaxf(v0, 0.f); v1 = fmaxf(v1, 0.f); }
                size_t idx = (size_t)r * N + c0;
                if (SPLIT) {
                    __nv_bfloat16 h0 = __float2bfloat16(v0);
                    __nv_bfloat16 h1 = __float2bfloat16(v1);
                    __nv_bfloat162 hp; hp.x = h0; hp.y = h1;
                    *reinterpret_cast<__nv_bfloat162*>(&Ch[idx]) = hp;
                    __nv_bfloat162 lp;
                    lp.x = __float2bfloat16(v0 - __bfloat162float(h0));
                    lp.y = __float2bfloat16(v1 - __bfloat162float(h1));
                    *reinterpret_cast<__nv_bfloat162*>(&Cl[idx]) = lp;
                } else {
                    *reinterpret_cast<float2*>(&C[idx]) = make_float2(v0, v1);
                }
            }
        }
    }
}

// ---------------------------------------------------------------------------
// Attention: Br=64, 128 threads (R13 shape), 2-stage pipelined K/V ring.
// Q staged into stage-0 alias (dead after fragment load). 3 CTAs/SM.
// ---------------------------------------------------------------------------
#define APAD 72
#define ATILE (64 * APAD)
#define AKV_STAGE (4 * ATILE)                       // Kh,Kl,Vh,Vl per stage
#define ATT_SMEM_BYTES (2 * AKV_STAGE * 2 + 2 * 64 * 4)

__global__ __launch_bounds__(128) void attn_mma(
    const __nv_bfloat16* __restrict__ Qh, const __nv_bfloat16* __restrict__ Ql,
    const __nv_bfloat16* __restrict__ Kh, const __nv_bfloat16* __restrict__ Kl,
    const __nv_bfloat16* __restrict__ Vh, const __nv_bfloat16* __restrict__ Vl,
    const int* __restrict__ mask,
    __nv_bfloat16* __restrict__ Oh, __nv_bfloat16* __restrict__ Ol, int ldin)
{
    extern __shared__ __align__(16) __nv_bfloat16 smb[];
    int* Msb = (int*)(smb + 2 * AKV_STAGE);          // [2][64]
    // Q staging aliases stage 0 (Kh/Kl slots)
    __nv_bfloat16* sQh = smb;
    __nv_bfloat16* sQl = smb + ATILE;

    const int qt = blockIdx.x, h = blockIdx.y, b = blockIdx.z;
    const int tid = threadIdx.x, lane = tid & 31, warp = tid >> 5, l16 = lane & 15;
    const size_t rowbase = (size_t)b * S_LEN + qt * 64;
    const int ch = h * DK;
    const int nt = S_LEN / 64;

    // Stage Q (hi+lo)
    for (int i = tid; i < 512; i += 128) {
        int r = i >> 3, c8 = (i & 7) * 8;
        size_t g = (rowbase + r) * (size_t)ldin + ch + c8;
        cp16(&sQh[r * APAD + c8], Qh + g);
        cp16(&sQl[r * APAD + c8], Ql + g);
    }
    asm volatile("cp.async.commit_group;\n" ::: "memory");
    asm volatile("cp.async.wait_group 0;\n" ::: "memory");
    __syncthreads();

    uint32_t qfh[4][4], qfl[4][4];
#pragma unroll
    for (int kc = 0; kc < 4; kc++) {
        int row = warp * 16 + l16, col = kc * 16 + (lane >> 4) * 8;
        ldsm_x4(qfh[kc], &sQh[row * APAD + col]);
        ldsm_x4(qfl[kc], &sQl[row * APAD + col]);
    }
    __syncthreads();   // Q frags consumed; stage 0 reusable

    auto issue_kv = [&](int c) {
        __nv_bfloat16* st = smb + (c & 1) * AKV_STAGE;
        for (int i = tid; i < 512; i += 128) {
            int r = i >> 3, c8 = (i & 7) * 8;
            size_t g = ((size_t)b * S_LEN + c * 64 + r) * (size_t)ldin + ch + c8;
            int so = r * APAD + c8;
            cp16(st + so, Kh + g);
            cp16(st + ATILE + so, Kl + g);
            cp16(st + 2 * ATILE + so, Vh + g);
            cp16(st + 3 * ATILE + so, Vl + g);
        }
        if (tid < 64)
            Msb[(c & 1) * 64 + tid] = mask[(size_t)b * S_LEN + c * 64 + tid];
        asm volatile("cp.async.commit_group;\n" ::: "memory");
    };

    issue_kv(0);
    issue_kv(1);

    float m0 = -1e30f, m1 = -1e30f, l0 = 0.f, l1 = 0.f;
    float o[8][4];
#pragma unroll
    for (int nf = 0; nf < 8; nf++)
#pragma unroll
        for (int j = 0; j < 4; j++) o[nf][j] = 0.f;

    for (int kt = 0; kt < nt; kt++) {
        if (kt + 2 < nt) {
            asm volatile("cp.async.wait_group 1;\n" ::: "memory");
        } else {
            asm volatile("cp.async.wait_group 0;\n" ::: "memory");
        }
        __syncthreads();

        __nv_bfloat16* st = smb + (kt & 1) * AKV_STAGE;
        __nv_bfloat16* sKh = st;
        __nv_bfloat16* sKl = st + ATILE;
        __nv_bfloat16* sVh = st + 2 * ATILE;
        __nv_bfloat16* sVl = st + 3 * ATILE;
        int* Ms = Msb + (kt & 1) * 64;

        float s[8][4];
#pragma unroll
        for (int nf = 0; nf < 8; nf++)
#pragma unroll
            for (int j = 0; j < 4; j++) s[nf][j] = 0.f;

#pragma unroll
        for (int kc = 0; kc < 4; kc++) {
            int rr = (l16 & 7), cc = kc * 16 + (l16 >> 3) * 8;
#pragma unroll
            for (int nf = 0; nf < 8; nf++) {
                uint32_t bh[2];
                ldsm_x2(bh, &sKh[(nf * 8 + rr) * APAD + cc]);
                mma_16816(s[nf], qfh[kc], bh);
                mma_16816(s[nf], qfl[kc], bh);
            }
#pragma unroll
            for (int nf = 0; nf < 8; nf++) {
                uint32_t bl[2];
                ldsm_x2(bl, &sKl[(nf * 8 + rr) * APAD + cc]);
                mma_16816(s[nf], qfh[kc], bl);
            }
        }

#pragma unroll
        for (int nf = 0; nf < 8; nf++) {
            int c0 = nf * 8 + (lane & 3) * 2;
            bool z0 = (Ms[c0] == 0), z1 = (Ms[c0 + 1] == 0);
            s[nf][0] = z0 ? -1e9f : s[nf][0] * 0.125f;
            s[nf][1] = z1 ? -1e9f : s[nf][1] * 0.125f;
            s[nf][2] = z0 ? -1e9f : s[nf][2] * 0.125f;
            s[nf][3] = z1 ? -1e9f : s[nf][3] * 0.125f;
        }

        float tm0 = -1e30f, tm1 = -1e30f;
#pragma unroll
        for (int nf = 0; nf < 8; nf++) {
            tm0 = fmaxf(tm0, fmaxf(s[nf][0], s[nf][1]));
            tm1 = fmaxf(tm1, fmaxf(s[nf][2], s[nf][3]));
        }
        tm0 = fmaxf(tm0, __shfl_xor_sync(0xffffffffu, tm0, 1));
        tm0 = fmaxf(tm0, __shfl_xor_sync(0xffffffffu, tm0, 2));
        tm1 = fmaxf(tm1, __shfl_xor_sync(0xffffffffu, tm1, 1));
        tm1 = fmaxf(tm1, __shfl_xor_sync(0xffffffffu, tm1, 2));

        float mn0 = fmaxf(m0, tm0), mn1 = fmaxf(m1, tm1);
        float sc0 = __expf(m0 - mn0), sc1 = __expf(m1 - mn1);
        m0 = mn0; m1 = mn1;

        float ts0 = 0.f, ts1 = 0.f;
#pragma unroll
        for (int nf = 0; nf < 8; nf++) {
            s[nf][0] = __expf(s[nf][0] - m0);
            s[nf][1] = __expf(s[nf][1] - m0);
            s[nf][2] = __expf(s[nf][2] - m1);
            s[nf][3] = __expf(s[nf][3] - m1);
            ts0 += s[nf][0] + s[nf][1];
            ts1 += s[nf][2] + s[nf][3];
        }
        ts0 += __shfl_xor_sync(0xffffffffu, ts0, 1);
        ts0 += __shfl_xor_sync(0xffffffffu, ts0, 2);
        ts1 += __shfl_xor_sync(0xffffffffu, ts1, 1);
        ts1 += __shfl_xor_sync(0xffffffffu, ts1, 2);
        l0 = l0 * sc0 + ts0;
        l1 = l1 * sc1 + ts1;

#pragma unroll
        for (int nf = 0; nf < 8; nf++) {
            o[nf][0] *= sc0; o[nf][1] *= sc0;
            o[nf][2] *= sc1; o[nf][3] *= sc1;
        }

#pragma unroll
        for (int j = 0; j < 4; j++) {
            uint32_t ah[4], al[4];
#pragma unroll
            for (int half = 0; half < 2; half++) {
                const float* p = s[2 * j + half];
#pragma unroll
                for (int rr2 = 0; rr2 < 2; rr2++) {
                    float p0 = p[rr2 * 2 + 0], p1 = p[rr2 * 2 + 1];
                    __nv_bfloat16 h0 = __float2bfloat16(p0), h1 = __float2bfloat16(p1);
                    __nv_bfloat162 hp; hp.x = h0; hp.y = h1;
                    ah[half * 2 + rr2] = *reinterpret_cast<uint32_t*>(&hp);
                    al[half * 2 + rr2] = pack_bf16(p0 - __bfloat162float(h0),
                                                   p1 - __bfloat162float(h1));
                }
            }
            int vrow = j * 16 + l16;
#pragma unroll
            for (int nf = 0; nf < 8; nf++) {
                uint32_t bvh[2];
                ldsm_x2t(bvh, &sVh[vrow * APAD + nf * 8]);
                mma_16816(o[nf], ah, bvh);
                mma_16816(o[nf], al, bvh);
            }
#pragma unroll
            for (int nf = 0; nf < 8; nf++) {
                uint32_t bvl[2];
                ldsm_x2t(bvl, &sVl[vrow * APAD + nf * 8]);
                mma_16816(o[nf], ah, bvl);
            }
        }

        __syncthreads();   // done reading this stage
        if (kt + 2 < nt) issue_kv(kt + 2);
    }

    float inv0 = 1.f / l0, inv1 = 1.f / l1;
    int r0 = warp * 16 + (lane >> 2);
#pragma unroll
    for (int nf = 0; nf < 8; nf++) {
        int c0 = ch + nf * 8 + (lane & 3) * 2;
#pragma unroll
        for (int hh = 0; hh < 2; hh++) {
            float v0 = o[nf][hh * 2 + 0] * (hh ? inv1 : inv0);
            float v1 = o[nf][hh * 2 + 1] * (hh ? inv1 : inv0);
            size_t idx = (rowbase + r0 + hh * 8) * D_MODEL + c0;
            __nv_bfloat16 h0 = __float2bfloat16(v0), h1 = __float2bfloat16(v1);
            __nv_bfloat162 hp; hp.x = h0; hp.y = h1;
            *reinterpret_cast<__nv_bfloat162*>(&Oh[idx]) = hp;
            __nv_bfloat162 lp;
            lp.x = __float2bfloat16(v0 - __bfloat162float(h0));
            lp.y = __float2bfloat16(v1 - __bfloat162float(h1));
            *reinterpret_cast<__nv_bfloat162*>(&Ol[idx]) = lp;
        }
    }
}

// ---------------- residual + LayerNorm ----------------
template <bool SPLITOUT>
__global__ __launch_bounds__(256) void add_ln_kernel(
    const float* __restrict__ A, const float* __restrict__ Bp,
    const float* __restrict__ alpha, const float* __restrict__ beta,
    float* __restrict__ out, __nv_bfloat16* __restrict__ oh,
    __nv_bfloat16* __restrict__ ol)
{
    __shared__ float buf[D_MODEL];
    __shared__ float red_s[8], red_q[8];
    __shared__ float sh_mean, sh_inv;
    const int row = blockIdx.x, tid = threadIdx.x;
    const size_t base = (size_t)row * D_MODEL;

    float s = 0.f, q = 0.f;
    for (int c = tid; c < D_MODEL; c += 256) {
        float v = A[base + c] + Bp[base + c];
        buf[c] = v; s += v; q = fmaf(v, v, q);
    }
#pragma unroll
    for (int msk = 16; msk >= 1; msk >>= 1) {
        s += __shfl_xor_sync(0xffffffffu, s, msk);
        q += __shfl_xor_sync(0xffffffffu, q, msk);
    }
    if ((tid & 31) == 0) { red_s[tid >> 5] = s; red_q[tid >> 5] = q; }
    __syncthreads();
    if (tid == 0) {
        float S = 0.f, Q = 0.f;
#pragma unroll
        for (int i = 0; i < 8; i++) { S += red_s[i]; Q += red_q[i]; }
        float mean = S * (1.f / (float)D_MODEL);
        float var = fmaxf((Q - (float)D_MODEL * mean * mean) *
                          (1.f / (float)(D_MODEL - 1)), 0.f);
        sh_mean = mean;
        sh_inv = 1.f / (sqrtf(var) + 1e-6f);
    }
    __syncthreads();
    const float mean = sh_mean, inv = sh_inv;
    for (int c = tid; c < D_MODEL; c += 256) {
        float v = fmaf(alpha[c], (buf[c] - mean) * inv, beta[c]);
        out[base + c] = v;
        if (SPLITOUT) {
            __nv_bfloat16 hv = __float2bfloat16(v);
            oh[base + c] = hv;
            ol[base + c] = __float2bfloat16(v - __bfloat162float(hv));
        }
    }
}

// ---------------- launch ----------------
extern "C" void kernel_launch(void* const* d_in, const int* in_sizes, int n_in,
                              void* d_out, int out_size)
{
    const float* x   = (const float*)d_in[0];
    const int* mask  = (const int*)d_in[1];
    const float* w_q = (const float*)d_in[2];
    const float* w_k = (const float*)d_in[3];
    const float* w_v = (const float*)d_in[4];
    const float* w_o = (const float*)d_in[5];
    const float* W1  = (const float*)d_in[6];
    const float* b1  = (const float*)d_in[7];
    const float* W2  = (const float*)d_in[8];
    const float* b2  = (const float*)d_in[9];
    const float* a1  = (const float*)d_in[10];
    const float* be1 = (const float*)d_in[11];
    const float* a2  = (const float*)d_in[12];
    const float* be2 = (const float*)d_in[13];
    float* out = (float*)d_out;

    float *O, *X1;
    cudaGetSymbolAddress((void**)&O, g_O);
    cudaGetSymbolAddress((void**)&X1, g_X1);
    __nv_bfloat16 *xh, *xl, *qkvh, *qkvl, *wqkvh, *wqkvl, *woh, *wol;
    __nv_bfloat16 *W1h, *W1l, *W2h, *W2l, *aoh, *aol, *x1h, *x1l, *Hh, *Hl;
    cudaGetSymbolAddress((void**)&xh, g_xh);       cudaGetSymbolAddress((void**)&xl, g_xl);
    cudaGetSymbolAddress((void**)&qkvh, g_qkvh);   cudaGetSymbolAddress((void**)&qkvl, g_qkvl);
    cudaGetSymbolAddress((void**)&wqkvh, g_wqkvh); cudaGetSymbolAddress((void**)&wqkvl, g_wqkvl);
    cudaGetSymbolAddress((void**)&woh, g_woh);     cudaGetSymbolAddress((void**)&wol, g_wol);
    cudaGetSymbolAddress((void**)&W1h, g_W1h);     cudaGetSymbolAddress((void**)&W1l, g_W1l);
    cudaGetSymbolAddress((void**)&W2h, g_W2h);     cudaGetSymbolAddress((void**)&W2l, g_W2l);
    cudaGetSymbolAddress((void**)&aoh, g_aoh);     cudaGetSymbolAddress((void**)&aol, g_aol);
    cudaGetSymbolAddress((void**)&x1h, g_x1h);     cudaGetSymbolAddress((void**)&x1l, g_x1l);
    cudaGetSymbolAddress((void**)&Hh, g_Hh);       cudaGetSymbolAddress((void**)&Hl, g_Hl);

    cudaFuncSetAttribute(attn_mma, cudaFuncAttributeMaxDynamicSharedMemorySize,
                         ATT_SMEM_BYTES);
    cudaFuncSetAttribute(hgemm_fused<false, false, true>,
                         cudaFuncAttributeMaxDynamicSharedMemorySize, GSMEM_TOTAL);
    cudaFuncSetAttribute(hgemm_fused<false, false, false>,
                         cudaFuncAttributeMaxDynamicSharedMemorySize, GSMEM_TOTAL);
    cudaFuncSetAttribute(hgemm_fused<true, true, true>,
                         cudaFuncAttributeMaxDynamicSharedMemorySize, GSMEM_TOTAL);
    cudaFuncSetAttribute(hgemm_fused<true, false, false>,
                         cudaFuncAttributeMaxDynamicSharedMemorySize, GSMEM_TOTAL);

    const dim3 blk(256);
    const dim3 gQKV(D3 / 128, ROWS / 128);
    const dim3 gP(D_MODEL / 128, ROWS / 128);
    const dim3 gF(DFF / 128, ROWS / 128);

    // 1: split x; 2: qkv weight split; 3: QKV GEMM; 4: attention (profiled)
    split4_kernel<<<RM / 4096, blk>>>((const float4*)x, xh, xl, RM / 4);
    split_qkv_kernel<<<dim3(MM / 1024, 1, 3), blk>>>(
        (const float4*)w_q, (const float4*)w_k, (const float4*)w_v, wqkvh, wqkvl);

    hgemm_fused<false, false, true><<<gQKV, blk, GSMEM_TOTAL>>>(
        xh, xl, wqkvh, wqkvl, nullptr, nullptr, qkvh, qkvl, ROWS, D3, D_MODEL);

    attn_mma<<<dim3(S_LEN / 64, HEADS, BATCH), 128, ATT_SMEM_BYTES>>>(
        qkvh, qkvl, qkvh + D_MODEL, qkvl + D_MODEL,
        qkvh + 2 * D_MODEL, qkvl + 2 * D_MODEL, mask, aoh, aol, D3);

    split4_kernel<<<MM / 4096, blk>>>((const float4*)w_o, woh, wol, MM / 4);
    split4_kernel<<<MF / 4096, blk>>>((const float4*)W1, W1h, W1l, MF / 4);
    split4_kernel<<<MF / 4096, blk>>>((const float4*)W2, W2h, W2l, MF / 4);

    hgemm_fused<false, false, false><<<gP, blk, GSMEM_TOTAL>>>(
        aoh, aol, woh, wol, nullptr, O, nullptr, nullptr, ROWS, D_MODEL, D_MODEL);

    add_ln_kernel<true><<<ROWS, blk>>>(x, O, a1, be1, X1, x1h, x1l);

    hgemm_fused<true, true, true><<<gF, blk, GSMEM_TOTAL>>>(
        x1h, x1l, W1h, W1l, b1, nullptr, Hh, Hl, ROWS, DFF, D_MODEL);

    hgemm_fused<true, false, false><<<gP, blk, GSMEM_TOTAL>>>(
        Hh, Hl, W2h, W2l, b2, O, nullptr, nullptr, ROWS, D_MODEL, DFF);

    add_ln_kernel<false><<<ROWS, blk>>>(X1, O, a2, be2, out, nullptr, nullptr);
}

// round 16
// speedup vs baseline: 1.0150x; 1.0064x over previous
#include <cuda_runtime.h>
#include <cuda_bf16.h>
#include <math.h>
#include <stdint.h>

#define D_MODEL 1024
#define S_LEN   2048
#define BATCH   2
#define HEADS   16
#define DK      64
#define DFF     4096
#define ROWS    4096
#define D3      3072

#define RM (ROWS * D_MODEL)
#define R3 (ROWS * D3)
#define MM (D_MODEL * D_MODEL)
#define MF (D_MODEL * DFF)
#define RF (ROWS * DFF)

__device__ float g_O [RM];
__device__ float g_X1[RM];
__device__ __nv_bfloat16 g_xh [RM], g_xl [RM];
__device__ __nv_bfloat16 g_qkvh[R3], g_qkvl[R3];
__device__ __nv_bfloat16 g_wqkvh[D_MODEL * D3], g_wqkvl[D_MODEL * D3];
__device__ __nv_bfloat16 g_woh[MM], g_wol[MM];
__device__ __nv_bfloat16 g_W1h[MF], g_W1l[MF];
__device__ __nv_bfloat16 g_W2h[MF], g_W2l[MF];
__device__ __nv_bfloat16 g_aoh[RM], g_aol[RM];
__device__ __nv_bfloat16 g_x1h[RM], g_x1l[RM];
__device__ __nv_bfloat16 g_Hh [RF], g_Hl [RF];

// ---------------- helpers ----------------
__device__ __forceinline__ uint32_t pack_bf16(float a, float b)
{
    __nv_bfloat162 t; t.x = __float2bfloat16(a); t.y = __float2bfloat16(b);
    return *reinterpret_cast<uint32_t*>(&t);
}
__device__ __forceinline__ void mma_16816(float* c, const uint32_t* a, const uint32_t* b)
{
    asm volatile(
        "mma.sync.aligned.m16n8k16.row.col.f32.bf16.bf16.f32 "
        "{%0,%1,%2,%3}, {%4,%5,%6,%7}, {%8,%9}, {%0,%1,%2,%3};\n"
        : "+f"(c[0]), "+f"(c[1]), "+f"(c[2]), "+f"(c[3])
        : "r"(a[0]), "r"(a[1]), "r"(a[2]), "r"(a[3]), "r"(b[0]), "r"(b[1]));
}
__device__ __forceinline__ void cp16(void* d, const void* s)
{
    uint32_t a = (uint32_t)__cvta_generic_to_shared(d);
    asm volatile("cp.async.cg.shared.global [%0], [%1], 16;\n" :: "r"(a), "l"(s));
}
__device__ __forceinline__ void ldsm_x4(uint32_t* r, const void* p)
{
    uint32_t a = (uint32_t)__cvta_generic_to_shared(p);
    asm volatile("ldmatrix.sync.aligned.m8n8.x4.shared.b16 {%0,%1,%2,%3}, [%4];\n"
                 : "=r"(r[0]), "=r"(r[1]), "=r"(r[2]), "=r"(r[3]) : "r"(a));
}
__device__ __forceinline__ void ldsm_x4t(uint32_t* r, const void* p)
{
    uint32_t a = (uint32_t)__cvta_generic_to_shared(p);
    asm volatile("ldmatrix.sync.aligned.m8n8.x4.trans.shared.b16 {%0,%1,%2,%3}, [%4];\n"
                 : "=r"(r[0]), "=r"(r[1]), "=r"(r[2]), "=r"(r[3]) : "r"(a));
}
__device__ __forceinline__ void ldsm_x2(uint32_t* r, const void* p)
{
    uint32_t a = (uint32_t)__cvta_generic_to_shared(p);
    asm volatile("ldmatrix.sync.aligned.m8n8.x2.shared.b16 {%0,%1}, [%2];\n"
                 : "=r"(r[0]), "=r"(r[1]) : "r"(a));
}
__device__ __forceinline__ void ldsm_x2t(uint32_t* r, const void* p)
{
    uint32_t a = (uint32_t)__cvta_generic_to_shared(p);
    asm volatile("ldmatrix.sync.aligned.m8n8.x2.trans.shared.b16 {%0,%1}, [%2];\n"
                 : "=r"(r[0]), "=r"(r[1]) : "r"(a));
}

// ---------------- splits ----------------
__device__ __forceinline__ void split_store(
    __nv_bfloat16* hi, __nv_bfloat16* lo, size_t e, float4 v)
{
    __nv_bfloat16 h0 = __float2bfloat16(v.x), h1 = __float2bfloat16(v.y);
    __nv_bfloat16 h2 = __float2bfloat16(v.z), h3 = __float2bfloat16(v.w);
    __nv_bfloat162 a; a.x = h0; a.y = h1;
    __nv_bfloat162 b; b.x = h2; b.y = h3;
    uint2 hp;
    hp.x = *reinterpret_cast<uint32_t*>(&a);
    hp.y = *reinterpret_cast<uint32_t*>(&b);
    *reinterpret_cast<uint2*>(&hi[e]) = hp;
    uint2 lp;
    lp.x = pack_bf16(v.x - __bfloat162float(h0), v.y - __bfloat162float(h1));
    lp.y = pack_bf16(v.z - __bfloat162float(h2), v.w - __bfloat162float(h3));
    *reinterpret_cast<uint2*>(&lo[e]) = lp;
}

__global__ __launch_bounds__(256) void split4_kernel(
    const float4* __restrict__ x, __nv_bfloat16* __restrict__ hi,
    __nv_bfloat16* __restrict__ lo, int n4)
{
    const int stride = gridDim.x * 256;
    const int i = blockIdx.x * 256 + threadIdx.x;
    float4 v[4];
#pragma unroll
    for (int k = 0; k < 4; k++) {
        int idx = i + k * stride;
        if (idx < n4) v[k] = x[idx];
    }
#pragma unroll
    for (int k = 0; k < 4; k++) {
        int idx = i + k * stride;
        if (idx < n4) split_store(hi, lo, (size_t)idx * 4, v[k]);
    }
}

__global__ __launch_bounds__(256) void split_qkv_kernel(
    const float4* __restrict__ wq, const float4* __restrict__ wk,
    const float4* __restrict__ wv,
    __nv_bfloat16* __restrict__ hi, __nv_bfloat16* __restrict__ lo)
{
    const int which = blockIdx.z;
    const float4* src = (which == 0) ? wq : (which == 1) ? wk : wv;
    int i = blockIdx.x * 256 + threadIdx.x;
    if (i >= MM / 4) return;
    float4 v = src[i];
    int e = i * 4;
    int row = e >> 10, col = e & 1023;
    size_t o = (size_t)row * D3 + which * D_MODEL + col;
    split_store(hi, lo, o, v);
}

// ---------------------------------------------------------------------------
// Fused split-3 bf16 GEMM (best/R10 config). Optional fp32 residual add in
// the non-split epilogue (commutative add -> bit-identical to LN-side add).
// ---------------------------------------------------------------------------
#define GA_ROW 40
#define GB_ROW 136
#define A_BYTES (128 * GA_ROW * 2)
#define B_BYTES (32 * GB_ROW * 2)
#define STAGE_BYTES (2 * A_BYTES + 2 * B_BYTES)
#define GSMEM_TOTAL (3 * STAGE_BYTES)

template <bool BIAS, bool RELU, bool SPLIT>
__global__ __launch_bounds__(256, 2) void hgemm_fused(
    const __nv_bfloat16* __restrict__ Ah_, const __nv_bfloat16* __restrict__ Al_,
    const __nv_bfloat16* __restrict__ Bh_, const __nv_bfloat16* __restrict__ Bl_,
    const float* __restrict__ bias, const float* __restrict__ resid,
    float* __restrict__ C,
    __nv_bfloat16* __restrict__ Ch, __nv_bfloat16* __restrict__ Cl,
    int M, int N, int K)
{
    extern __shared__ __align__(16) char gsm[];
    auto As = [&](int hl, int s) {
        return (__nv_bfloat16*)(gsm + s * STAGE_BYTES + hl * A_BYTES);
    };
    auto Bs = [&](int hl, int s) {
        return (__nv_bfloat16*)(gsm + s * STAGE_BYTES + 2 * A_BYTES + hl * B_BYTES);
    };

    const int tid  = threadIdx.x;
    const int lane = tid & 31;
    const int warp = tid >> 5;
    const int wm   = warp & 3;
    const int wn   = warp >> 2;
    const int rowBase = blockIdx.y * 128;
    const int colBase = blockIdx.x * 128;
    const int nc = K / 32;

    float acc[2][8][4];
#pragma unroll
    for (int i = 0; i < 2; i++)
#pragma unroll
        for (int j = 0; j < 8; j++)
#pragma unroll
            for (int k = 0; k < 4; k++) acc[i][j][k] = 0.f;

    auto issue = [&](int c) {
        int s = c % 3, k0 = c * 32;
#pragma unroll
        for (int i = 0; i < 2; i++) {
            int t = tid * 2 + i;
            int r = t >> 2, c8 = (t & 3) * 8;
            const size_t g = (size_t)(rowBase + r) * K + k0 + c8;
            cp16(As(0, s) + r * GA_ROW + c8, Ah_ + g);
            cp16(As(1, s) + r * GA_ROW + c8, Al_ + g);
        }
#pragma unroll
        for (int i = 0; i < 2; i++) {
            int t = tid + i * 256;
            int r = t >> 4, c8 = (t & 15) * 8;
            const size_t g = (size_t)(k0 + r) * N + colBase + c8;
            cp16(Bs(0, s) + r * GB_ROW + c8, Bh_ + g);
            cp16(Bs(1, s) + r * GB_ROW + c8, Bl_ + g);
        }
        asm volatile("cp.async.commit_group;\n" ::: "memory");
    };

    issue(0);
    issue(1);
    for (int c = 0; c < nc; c++) {
        const int s = c % 3;
        if (c + 2 < nc) {
            asm volatile("cp.async.wait_group 1;\n" ::: "memory");
        } else {
            asm volatile("cp.async.wait_group 0;\n" ::: "memory");
        }
        __syncthreads();
        if (c + 2 < nc) issue(c + 2);

#pragma unroll
        for (int ks = 0; ks < 32; ks += 16) {
            uint32_t ahf[2][4], alf[2][4];
#pragma unroll
            for (int fm = 0; fm < 2; fm++) {
                int row = wm * 32 + fm * 16 + (lane & 15);
                int col = ks + ((lane >> 4) << 3);
                ldsm_x4(ahf[fm], As(0, s) + row * GA_ROW + col);
                ldsm_x4(alf[fm], As(1, s) + row * GA_ROW + col);
            }
            const int brow = ks + (lane & 7) + ((lane >> 3) & 1) * 8;
            const int bcof = (lane >> 4) * 8;
#pragma unroll
            for (int fnp = 0; fnp < 4; fnp++) {
                const int bcol = wn * 64 + fnp * 16 + bcof;
                uint32_t bh4[4];
                ldsm_x4t(bh4, Bs(0, s) + brow * GB_ROW + bcol);
#pragma unroll
                for (int fm = 0; fm < 2; fm++) {
                    mma_16816(acc[fm][2 * fnp],     ahf[fm], bh4 + 0);
                    mma_16816(acc[fm][2 * fnp + 1], ahf[fm], bh4 + 2);
                }
#pragma unroll
                for (int fm = 0; fm < 2; fm++) {
                    mma_16816(acc[fm][2 * fnp],     alf[fm], bh4 + 0);
                    mma_16816(acc[fm][2 * fnp + 1], alf[fm], bh4 + 2);
                }
                uint32_t bl4[4];
                ldsm_x4t(bl4, Bs(1, s) + brow * GB_ROW + bcol);
#pragma unroll
                for (int fm = 0; fm < 2; fm++) {
                    mma_16816(acc[fm][2 * fnp],     ahf[fm], bl4 + 0);
                    mma_16816(acc[fm][2 * fnp + 1], ahf[fm], bl4 + 2);
                }
            }
        }
        __syncthreads();
    }

#pragma unroll
    for (int fm = 0; fm < 2; fm++) {
#pragma unroll
        for (int fn = 0; fn < 8; fn++) {
            int r0 = rowBase + wm * 32 + fm * 16 + (lane >> 2);
            int c0 = colBase + wn * 64 + fn * 8 + (lane & 3) * 2;
            float bx = 0.f, by = 0.f;
            if (BIAS) { bx = bias[c0]; by = bias[c0 + 1]; }
#pragma unroll
            for (int hh = 0; hh < 2; hh++) {
                int r = r0 + hh * 8;
                float v0 = acc[fm][fn][hh * 2 + 0] + bx;
                float v1 = acc[fm][fn][hh * 2 + 1] + by;
                if (RELU) { v0 = fmaxf(v0, 0.f); v1 = fmaxf(v1, 0.f); }
                size_t idx = (size_t)r * N + c0;
                if (SPLIT) {
                    __nv_bfloat16 h0 = __float2bfloat16(v0);
                    __nv_bfloat16 h1 = __float2bfloat16(v1);
                    __nv_bfloat162 hp; hp.x = h0; hp.y = h1;
                    *reinterpret_cast<__nv_bfloat162*>(&Ch[idx]) = hp;
                    __nv_bfloat162 lp;
                    lp.x = __float2bfloat16(v0 - __bfloat162float(h0));
                    lp.y = __float2bfloat16(v1 - __bfloat162float(h1));
                    *reinterpret_cast<__nv_bfloat162*>(&Cl[idx]) = lp;
                } else {
                    if (resid != nullptr) {
                        float2 rv = *reinterpret_cast<const float2*>(&resid[idx]);
                        v0 += rv.x;
                        v1 += rv.y;
                    }
                    *reinterpret_cast<float2*>(&C[idx]) = make_float2(v0, v1);
                }
            }
        }
    }
}

// ---------------------------------------------------------------------------
// Attention (R13 config exactly): Br=64, 128 threads, single-stage K/V.
// ---------------------------------------------------------------------------
#define APAD 72
#define ATILE (64 * APAD)
#define ATT_SMEM_BYTES (6 * ATILE * 2 + 64 * 4)

__global__ __launch_bounds__(128) void attn_mma(
    const __nv_bfloat16* __restrict__ Qh, const __nv_bfloat16* __restrict__ Ql,
    const __nv_bfloat16* __restrict__ Kh, const __nv_bfloat16* __restrict__ Kl,
    const __nv_bfloat16* __restrict__ Vh, const __nv_bfloat16* __restrict__ Vl,
    const int* __restrict__ mask,
    __nv_bfloat16* __restrict__ Oh, __nv_bfloat16* __restrict__ Ol, int ldin)
{
    extern __shared__ __align__(16) __nv_bfloat16 smb[];
    __nv_bfloat16* sQh = smb;
    __nv_bfloat16* sQl = smb + ATILE;
    __nv_bfloat16* sKh = smb + 2 * ATILE;
    __nv_bfloat16* sKl = smb + 3 * ATILE;
    __nv_bfloat16* sVh = smb + 4 * ATILE;
    __nv_bfloat16* sVl = smb + 5 * ATILE;
    int* Ms = (int*)(smb + 6 * ATILE);

    const int qt = blockIdx.x, h = blockIdx.y, b = blockIdx.z;
    const int tid = threadIdx.x, lane = tid & 31, warp = tid >> 5, l16 = lane & 15;
    const size_t rowbase = (size_t)b * S_LEN + qt * 64;
    const int ch = h * DK;

    for (int i = tid; i < 512; i += 128) {
        int r = i >> 3, c8 = (i & 7) * 8;
        size_t g = (rowbase + r) * (size_t)ldin + ch + c8;
        cp16(&sQh[r * APAD + c8], Qh + g);
        cp16(&sQl[r * APAD + c8], Ql + g);
    }
    asm volatile("cp.async.commit_group;\n" ::: "memory");
    asm volatile("cp.async.wait_group 0;\n" ::: "memory");
    __syncthreads();

    uint32_t qfh[4][4], qfl[4][4];
#pragma unroll
    for (int kc = 0; kc < 4; kc++) {
        int row = warp * 16 + l16, col = kc * 16 + (lane >> 4) * 8;
        ldsm_x4(qfh[kc], &sQh[row * APAD + col]);
        ldsm_x4(qfl[kc], &sQl[row * APAD + col]);
    }

    float m0 = -1e30f, m1 = -1e30f, l0 = 0.f, l1 = 0.f;
    float o[8][4];
#pragma unroll
    for (int nf = 0; nf < 8; nf++)
#pragma unroll
        for (int j = 0; j < 4; j++) o[nf][j] = 0.f;

    for (int kt = 0; kt < S_LEN / 64; kt++) {
        __syncthreads();
        for (int i = tid; i < 512; i += 128) {
            int r = i >> 3, c8 = (i & 7) * 8;
            size_t g = ((size_t)b * S_LEN + kt * 64 + r) * (size_t)ldin + ch + c8;
            int so = r * APAD + c8;
            cp16(&sKh[so], Kh + g);
            cp16(&sKl[so], Kl + g);
            cp16(&sVh[so], Vh + g);
            cp16(&sVl[so], Vl + g);
        }
        if (tid < 64) Ms[tid] = mask[(size_t)b * S_LEN + kt * 64 + tid];
        asm volatile("cp.async.commit_group;\n" ::: "memory");
        asm volatile("cp.async.wait_group 0;\n" ::: "memory");
        __syncthreads();

        float s[8][4];
#pragma unroll
        for (int nf = 0; nf < 8; nf++)
#pragma unroll
            for (int j = 0; j < 4; j++) s[nf][j] = 0.f;

#pragma unroll
        for (int kc = 0; kc < 4; kc++) {
            int rr = (l16 & 7), cc = kc * 16 + (l16 >> 3) * 8;
#pragma unroll
            for (int nf = 0; nf < 8; nf++) {
                uint32_t bh[2];
                ldsm_x2(bh, &sKh[(nf * 8 + rr) * APAD + cc]);
                mma_16816(s[nf], qfh[kc], bh);
                mma_16816(s[nf], qfl[kc], bh);
            }
#pragma unroll
            for (int nf = 0; nf < 8; nf++) {
                uint32_t bl[2];
                ldsm_x2(bl, &sKl[(nf * 8 + rr) * APAD + cc]);
                mma_16816(s[nf], qfh[kc], bl);
            }
        }

#pragma unroll
        for (int nf = 0; nf < 8; nf++) {
            int c0 = nf * 8 + (lane & 3) * 2;
            bool z0 = (Ms[c0] == 0), z1 = (Ms[c0 + 1] == 0);
            s[nf][0] = z0 ? -1e9f : s[nf][0] * 0.125f;
            s[nf][1] = z1 ? -1e9f : s[nf][1] * 0.125f;
            s[nf][2] = z0 ? -1e9f : s[nf][2] * 0.125f;
            s[nf][3] = z1 ? -1e9f : s[nf][3] * 0.125f;
        }

        float tm0 = -1e30f, tm1 = -1e30f;
#pragma unroll
        for (int nf = 0; nf < 8; nf++) {
            tm0 = fmaxf(tm0, fmaxf(s[nf][0], s[nf][1]));
            tm1 = fmaxf(tm1, fmaxf(s[nf][2], s[nf][3]));
        }
        tm0 = fmaxf(tm0, __shfl_xor_sync(0xffffffffu, tm0, 1));
        tm0 = fmaxf(tm0, __shfl_xor_sync(0xffffffffu, tm0, 2));
        tm1 = fmaxf(tm1, __shfl_xor_sync(0xffffffffu, tm1, 1));
        tm1 = fmaxf(tm1, __shfl_xor_sync(0xffffffffu, tm1, 2));

        float mn0 = fmaxf(m0, tm0), mn1 = fmaxf(m1, tm1);
        float sc0 = __expf(m0 - mn0), sc1 = __expf(m1 - mn1);
        m0 = mn0; m1 = mn1;

        float ts0 = 0.f, ts1 = 0.f;
#pragma unroll
        for (int nf = 0; nf < 8; nf++) {
            s[nf][0] = __expf(s[nf][0] - m0);
            s[nf][1] = __expf(s[nf][1] - m0);
            s[nf][2] = __expf(s[nf][2] - m1);
            s[nf][3] = __expf(s[nf][3] - m1);
            ts0 += s[nf][0] + s[nf][1];
            ts1 += s[nf][2] + s[nf][3];
        }
        ts0 += __shfl_xor_sync(0xffffffffu, ts0, 1);
        ts0 += __shfl_xor_sync(0xffffffffu, ts0, 2);
        ts1 += __shfl_xor_sync(0xffffffffu, ts1, 1);
        ts1 += __shfl_xor_sync(0xffffffffu, ts1, 2);
        l0 = l0 * sc0 + ts0;
        l1 = l1 * sc1 + ts1;

#pragma unroll
        for (int nf = 0; nf < 8; nf++) {
            o[nf][0] *= sc0; o[nf][1] *= sc0;
            o[nf][2] *= sc1; o[nf][3] *= sc1;
        }

#pragma unroll
        for (int j = 0; j < 4; j++) {
            uint32_t ah[4], al[4];
#pragma unroll
            for (int half = 0; half < 2; half++) {
                const float* p = s[2 * j + half];
#pragma unroll
                for (int rr2 = 0; rr2 < 2; rr2++) {
                    float p0 = p[rr2 * 2 + 0], p1 = p[rr2 * 2 + 1];
                    __nv_bfloat16 h0 = __float2bfloat16(p0), h1 = __float2bfloat16(p1);
                    __nv_bfloat162 hp; hp.x = h0; hp.y = h1;
                    ah[half * 2 + rr2] = *reinterpret_cast<uint32_t*>(&hp);
                    al[half * 2 + rr2] = pack_bf16(p0 - __bfloat162float(h0),
                                                   p1 - __bfloat162float(h1));
                }
            }
            int vrow = j * 16 + l16;
#pragma unroll
            for (int nf = 0; nf < 8; nf++) {
                uint32_t bvh[2];
                ldsm_x2t(bvh, &sVh[vrow * APAD + nf * 8]);
                mma_16816(o[nf], ah, bvh);
                mma_16816(o[nf], al, bvh);
            }
#pragma unroll
            for (int nf = 0; nf < 8; nf++) {
                uint32_t bvl[2];
                ldsm_x2t(bvl, &sVl[vrow * APAD + nf * 8]);
                mma_16816(o[nf], ah, bvl);
            }
        }
    }

    float inv0 = 1.f / l0, inv1 = 1.f / l1;
    int r0 = warp * 16 + (lane >> 2);
#pragma unroll
    for (int nf = 0; nf < 8; nf++) {
        int c0 = ch + nf * 8 + (lane & 3) * 2;
#pragma unroll
        for (int hh = 0; hh < 2; hh++) {
            float v0 = o[nf][hh * 2 + 0] * (hh ? inv1 : inv0);
            float v1 = o[nf][hh * 2 + 1] * (hh ? inv1 : inv0);
            size_t idx = (rowbase + r0 + hh * 8) * D_MODEL + c0;
            __nv_bfloat16 h0 = __float2bfloat16(v0), h1 = __float2bfloat16(v1);
            __nv_bfloat162 hp; hp.x = h0; hp.y = h1;
            *reinterpret_cast<__nv_bfloat162*>(&Oh[idx]) = hp;
            __nv_bfloat162 lp;
            lp.x = __float2bfloat16(v0 - __bfloat162float(h0));
            lp.y = __float2bfloat16(v1 - __bfloat162float(h1));
            *reinterpret_cast<__nv_bfloat162*>(&Ol[idx]) = lp;
        }
    }
}

// ---------------- LayerNorm over a pre-summed buffer ----------------
template <bool SPLITOUT>
__global__ __launch_bounds__(256) void ln_kernel(
    const float* __restrict__ A,
    const float* __restrict__ alpha, const float* __restrict__ beta,
    float* __restrict__ out, __nv_bfloat16* __restrict__ oh,
    __nv_bfloat16* __restrict__ ol)
{
    __shared__ float buf[D_MODEL];
    __shared__ float red_s[8], red_q[8];
    __shared__ float sh_mean, sh_inv;
    const int row = blockIdx.x, tid = threadIdx.x;
    const size_t base = (size_t)row * D_MODEL;

    float s = 0.f, q = 0.f;
    for (int c = tid; c < D_MODEL; c += 256) {
        float v = A[base + c];
        buf[c] = v; s += v; q = fmaf(v, v, q);
    }
#pragma unroll
    for (int msk = 16; msk >= 1; msk >>= 1) {
        s += __shfl_xor_sync(0xffffffffu, s, msk);
        q += __shfl_xor_sync(0xffffffffu, q, msk);
    }
    if ((tid & 31) == 0) { red_s[tid >> 5] = s; red_q[tid >> 5] = q; }
    __syncthreads();
    if (tid == 0) {
        float S = 0.f, Q = 0.f;
#pragma unroll
        for (int i = 0; i < 8; i++) { S += red_s[i]; Q += red_q[i]; }
        float mean = S * (1.f / (float)D_MODEL);
        float var = fmaxf((Q - (float)D_MODEL * mean * mean) *
                          (1.f / (float)(D_MODEL - 1)), 0.f);
        sh_mean = mean;
        sh_inv = 1.f / (sqrtf(var) + 1e-6f);
    }
    __syncthreads();
    const float mean = sh_mean, inv = sh_inv;
    for (int c = tid; c < D_MODEL; c += 256) {
        float v = fmaf(alpha[c], (buf[c] - mean) * inv, beta[c]);
        out[base + c] = v;
        if (SPLITOUT) {
            __nv_bfloat16 hv = __float2bfloat16(v);
            oh[base + c] = hv;
            ol[base + c] = __float2bfloat16(v - __bfloat162float(hv));
        }
    }
}

// ---------------- launch ----------------
extern "C" void kernel_launch(void* const* d_in, const int* in_sizes, int n_in,
                              void* d_out, int out_size)
{
    const float* x   = (const float*)d_in[0];
    const int* mask  = (const int*)d_in[1];
    const float* w_q = (const float*)d_in[2];
    const float* w_k = (const float*)d_in[3];
    const float* w_v = (const float*)d_in[4];
    const float* w_o = (const float*)d_in[5];
    const float* W1  = (const float*)d_in[6];
    const float* b1  = (const float*)d_in[7];
    const float* W2  = (const float*)d_in[8];
    const float* b2  = (const float*)d_in[9];
    const float* a1  = (const float*)d_in[10];
    const float* be1 = (const float*)d_in[11];
    const float* a2  = (const float*)d_in[12];
    const float* be2 = (const float*)d_in[13];
    float* out = (float*)d_out;

    float *O, *X1;
    cudaGetSymbolAddress((void**)&O, g_O);
    cudaGetSymbolAddress((void**)&X1, g_X1);
    __nv_bfloat16 *xh, *xl, *qkvh, *qkvl, *wqkvh, *wqkvl, *woh, *wol;
    __nv_bfloat16 *W1h, *W1l, *W2h, *W2l, *aoh, *aol, *x1h, *x1l, *Hh, *Hl;
    cudaGetSymbolAddress((void**)&xh, g_xh);       cudaGetSymbolAddress((void**)&xl, g_xl);
    cudaGetSymbolAddress((void**)&qkvh, g_qkvh);   cudaGetSymbolAddress((void**)&qkvl, g_qkvl);
    cudaGetSymbolAddress((void**)&wqkvh, g_wqkvh); cudaGetSymbolAddress((void**)&wqkvl, g_wqkvl);
    cudaGetSymbolAddress((void**)&woh, g_woh);     cudaGetSymbolAddress((void**)&wol, g_wol);
    cudaGetSymbolAddress((void**)&W1h, g_W1h);     cudaGetSymbolAddress((void**)&W1l, g_W1l);
    cudaGetSymbolAddress((void**)&W2h, g_W2h);     cudaGetSymbolAddress((void**)&W2l, g_W2l);
    cudaGetSymbolAddress((void**)&aoh, g_aoh);     cudaGetSymbolAddress((void**)&aol, g_aol);
    cudaGetSymbolAddress((void**)&x1h, g_x1h);     cudaGetSymbolAddress((void**)&x1l, g_x1l);
    cudaGetSymbolAddress((void**)&Hh, g_Hh);       cudaGetSymbolAddress((void**)&Hl, g_Hl);

    cudaFuncSetAttribute(attn_mma, cudaFuncAttributeMaxDynamicSharedMemorySize,
                         ATT_SMEM_BYTES);
    cudaFuncSetAttribute(hgemm_fused<false, false, true>,
                         cudaFuncAttributeMaxDynamicSharedMemorySize, GSMEM_TOTAL);
    cudaFuncSetAttribute(hgemm_fused<false, false, false>,
                         cudaFuncAttributeMaxDynamicSharedMemorySize, GSMEM_TOTAL);
    cudaFuncSetAttribute(hgemm_fused<true, true, true>,
                         cudaFuncAttributeMaxDynamicSharedMemorySize, GSMEM_TOTAL);
    cudaFuncSetAttribute(hgemm_fused<true, false, false>,
                         cudaFuncAttributeMaxDynamicSharedMemorySize, GSMEM_TOTAL);

    const dim3 blk(256);
    const dim3 gQKV(D3 / 128, ROWS / 128);
    const dim3 gP(D_MODEL / 128, ROWS / 128);
    const dim3 gF(DFF / 128, ROWS / 128);

    // 1: split x; 2: qkv weight split; 3: QKV GEMM; 4: attention (profiled)
    split4_kernel<<<RM / 4096, blk>>>((const float4*)x, xh, xl, RM / 4);
    split_qkv_kernel<<<dim3(MM / 1024, 1, 3), blk>>>(
        (const float4*)w_q, (const float4*)w_k, (const float4*)w_v, wqkvh, wqkvl);

    hgemm_fused<false, false, true><<<gQKV, blk, GSMEM_TOTAL>>>(
        xh, xl, wqkvh, wqkvl, nullptr, nullptr, nullptr, qkvh, qkvl,
        ROWS, D3, D_MODEL);

    attn_mma<<<dim3(S_LEN / 64, HEADS, BATCH), 128, ATT_SMEM_BYTES>>>(
        qkvh, qkvl, qkvh + D_MODEL, qkvl + D_MODEL,
        qkvh + 2 * D_MODEL, qkvl + 2 * D_MODEL, mask, aoh, aol, D3);

    split4_kernel<<<MM / 4096, blk>>>((const float4*)w_o, woh, wol, MM / 4);
    split4_kernel<<<MF / 4096, blk>>>((const float4*)W1, W1h, W1l, MF / 4);
    split4_kernel<<<MF / 4096, blk>>>((const float4*)W2, W2h, W2l, MF / 4);

    // o-proj with fused residual (+x) -> O holds x + attn@w_o
    hgemm_fused<false, false, false><<<gP, blk, GSMEM_TOTAL>>>(
        aoh, aol, woh, wol, nullptr, x, O, nullptr, nullptr,
        ROWS, D_MODEL, D_MODEL);

    ln_kernel<true><<<ROWS, blk>>>(O, a1, be1, X1, x1h, x1l);

    hgemm_fused<true, true, true><<<gF, blk, GSMEM_TOTAL>>>(
        x1h, x1l, W1h, W1l, b1, nullptr, nullptr, Hh, Hl, ROWS, DFF, D_MODEL);

    // FFN2 with fused residual (+X1) -> O holds X1 + ffn_out
    hgemm_fused<true, false, false><<<gP, blk, GSMEM_TOTAL>>>(
        Hh, Hl, W2h, W2l, b2, X1, O, nullptr, nullptr, ROWS, D_MODEL, DFF);

    ln_kernel<false><<<ROWS, blk>>>(O, a2, be2, out, nullptr, nullptr);
}

// round 17
// speedup vs baseline: 1.0196x; 1.0046x over previous
#include <cuda_runtime.h>
#include <cuda_bf16.h>
#include <math.h>
#include <stdint.h>

#define D_MODEL 1024
#define S_LEN   2048
#define BATCH   2
#define HEADS   16
#define DK      64
#define DFF     4096
#define ROWS    4096
#define D3      3072

#define RM (ROWS * D_MODEL)
#define R3 (ROWS * D3)
#define MM (D_MODEL * D_MODEL)
#define MF (D_MODEL * DFF)
#define RF (ROWS * DFF)

__device__ float g_O [RM];
__device__ float g_X1[RM];
__device__ __nv_bfloat16 g_xh [RM], g_xl [RM];
__device__ __nv_bfloat16 g_qkvh[R3], g_qkvl[R3];
__device__ __nv_bfloat16 g_wqkvh[D_MODEL * D3], g_wqkvl[D_MODEL * D3];
__device__ __nv_bfloat16 g_woh[MM], g_wol[MM];
__device__ __nv_bfloat16 g_W1h[MF], g_W1l[MF];
__device__ __nv_bfloat16 g_W2h[MF], g_W2l[MF];
__device__ __nv_bfloat16 g_aoh[RM], g_aol[RM];
__device__ __nv_bfloat16 g_x1h[RM], g_x1l[RM];
__device__ __nv_bfloat16 g_Hh [RF], g_Hl [RF];

// ---------------- helpers ----------------
__device__ __forceinline__ uint32_t pack_bf16(float a, float b)
{
    __nv_bfloat162 t; t.x = __float2bfloat16(a); t.y = __float2bfloat16(b);
    return *reinterpret_cast<uint32_t*>(&t);
}
__device__ __forceinline__ void mma_16816(float* c, const uint32_t* a, const uint32_t* b)
{
    asm volatile(
        "mma.sync.aligned.m16n8k16.row.col.f32.bf16.bf16.f32 "
        "{%0,%1,%2,%3}, {%4,%5,%6,%7}, {%8,%9}, {%0,%1,%2,%3};\n"
        : "+f"(c[0]), "+f"(c[1]), "+f"(c[2]), "+f"(c[3])
        : "r"(a[0]), "r"(a[1]), "r"(a[2]), "r"(a[3]), "r"(b[0]), "r"(b[1]));
}
__device__ __forceinline__ void cp16(void* d, const void* s)
{
    uint32_t a = (uint32_t)__cvta_generic_to_shared(d);
    asm volatile("cp.async.cg.shared.global [%0], [%1], 16;\n" :: "r"(a), "l"(s));
}
__device__ __forceinline__ void ldsm_x4(uint32_t* r, const void* p)
{
    uint32_t a = (uint32_t)__cvta_generic_to_shared(p);
    asm volatile("ldmatrix.sync.aligned.m8n8.x4.shared.b16 {%0,%1,%2,%3}, [%4];\n"
                 : "=r"(r[0]), "=r"(r[1]), "=r"(r[2]), "=r"(r[3]) : "r"(a));
}
__device__ __forceinline__ void ldsm_x4t(uint32_t* r, const void* p)
{
    uint32_t a = (uint32_t)__cvta_generic_to_shared(p);
    asm volatile("ldmatrix.sync.aligned.m8n8.x4.trans.shared.b16 {%0,%1,%2,%3}, [%4];\n"
                 : "=r"(r[0]), "=r"(r[1]), "=r"(r[2]), "=r"(r[3]) : "r"(a));
}
__device__ __forceinline__ void ldsm_x2(uint32_t* r, const void* p)
{
    uint32_t a = (uint32_t)__cvta_generic_to_shared(p);
    asm volatile("ldmatrix.sync.aligned.m8n8.x2.shared.b16 {%0,%1}, [%2];\n"
                 : "=r"(r[0]), "=r"(r[1]) : "r"(a));
}
__device__ __forceinline__ void ldsm_x2t(uint32_t* r, const void* p)
{
    uint32_t a = (uint32_t)__cvta_generic_to_shared(p);
    asm volatile("ldmatrix.sync.aligned.m8n8.x2.trans.shared.b16 {%0,%1}, [%2];\n"
                 : "=r"(r[0]), "=r"(r[1]) : "r"(a));
}

// ---------------- splits ----------------
__device__ __forceinline__ void split_store(
    __nv_bfloat16* hi, __nv_bfloat16* lo, size_t e, float4 v)
{
    __nv_bfloat16 h0 = __float2bfloat16(v.x), h1 = __float2bfloat16(v.y);
    __nv_bfloat16 h2 = __float2bfloat16(v.z), h3 = __float2bfloat16(v.w);
    __nv_bfloat162 a; a.x = h0; a.y = h1;
    __nv_bfloat162 b; b.x = h2; b.y = h3;
    uint2 hp;
    hp.x = *reinterpret_cast<uint32_t*>(&a);
    hp.y = *reinterpret_cast<uint32_t*>(&b);
    *reinterpret_cast<uint2*>(&hi[e]) = hp;
    uint2 lp;
    lp.x = pack_bf16(v.x - __bfloat162float(h0), v.y - __bfloat162float(h1));
    lp.y = pack_bf16(v.z - __bfloat162float(h2), v.w - __bfloat162float(h3));
    *reinterpret_cast<uint2*>(&lo[e]) = lp;
}

__global__ __launch_bounds__(256) void split4_kernel(
    const float4* __restrict__ x, __nv_bfloat16* __restrict__ hi,
    __nv_bfloat16* __restrict__ lo, int n4)
{
    const int stride = gridDim.x * 256;
    const int i = blockIdx.x * 256 + threadIdx.x;
    float4 v[4];
#pragma unroll
    for (int k = 0; k < 4; k++) {
        int idx = i + k * stride;
        if (idx < n4) v[k] = x[idx];
    }
#pragma unroll
    for (int k = 0; k < 4; k++) {
        int idx = i + k * stride;
        if (idx < n4) split_store(hi, lo, (size_t)idx * 4, v[k]);
    }
}

__global__ __launch_bounds__(256) void split_qkv_kernel(
    const float4* __restrict__ wq, const float4* __restrict__ wk,
    const float4* __restrict__ wv,
    __nv_bfloat16* __restrict__ hi, __nv_bfloat16* __restrict__ lo)
{
    const int which = blockIdx.z;
    const float4* src = (which == 0) ? wq : (which == 1) ? wk : wv;
    int i = blockIdx.x * 256 + threadIdx.x;
    if (i >= MM / 4) return;
    float4 v = src[i];
    int e = i * 4;
    int row = e >> 10, col = e & 1023;
    size_t o = (size_t)row * D3 + which * D_MODEL + col;
    split_store(hi, lo, o, v);
}

// ---------------------------------------------------------------------------
// Fused split-3 bf16 GEMM (best config; optional fused fp32 residual).
// ---------------------------------------------------------------------------
#define GA_ROW 40
#define GB_ROW 136
#define A_BYTES (128 * GA_ROW * 2)
#define B_BYTES (32 * GB_ROW * 2)
#define STAGE_BYTES (2 * A_BYTES + 2 * B_BYTES)
#define GSMEM_TOTAL (3 * STAGE_BYTES)

template <bool BIAS, bool RELU, bool SPLIT>
__global__ __launch_bounds__(256, 2) void hgemm_fused(
    const __nv_bfloat16* __restrict__ Ah_, const __nv_bfloat16* __restrict__ Al_,
    const __nv_bfloat16* __restrict__ Bh_, const __nv_bfloat16* __restrict__ Bl_,
    const float* __restrict__ bias, const float* __restrict__ resid,
    float* __restrict__ C,
    __nv_bfloat16* __restrict__ Ch, __nv_bfloat16* __restrict__ Cl,
    int M, int N, int K)
{
    extern __shared__ __align__(16) char gsm[];
    auto As = [&](int hl, int s) {
        return (__nv_bfloat16*)(gsm + s * STAGE_BYTES + hl * A_BYTES);
    };
    auto Bs = [&](int hl, int s) {
        return (__nv_bfloat16*)(gsm + s * STAGE_BYTES + 2 * A_BYTES + hl * B_BYTES);
    };

    const int tid  = threadIdx.x;
    const int lane = tid & 31;
    const int warp = tid >> 5;
    const int wm   = warp & 3;
    const int wn   = warp >> 2;
    const int rowBase = blockIdx.y * 128;
    const int colBase = blockIdx.x * 128;
    const int nc = K / 32;

    float acc[2][8][4];
#pragma unroll
    for (int i = 0; i < 2; i++)
#pragma unroll
        for (int j = 0; j < 8; j++)
#pragma unroll
            for (int k = 0; k < 4; k++) acc[i][j][k] = 0.f;

    auto issue = [&](int c) {
        int s = c % 3, k0 = c * 32;
#pragma unroll
        for (int i = 0; i < 2; i++) {
            int t = tid * 2 + i;
            int r = t >> 2, c8 = (t & 3) * 8;
            const size_t g = (size_t)(rowBase + r) * K + k0 + c8;
            cp16(As(0, s) + r * GA_ROW + c8, Ah_ + g);
            cp16(As(1, s) + r * GA_ROW + c8, Al_ + g);
        }
#pragma unroll
        for (int i = 0; i < 2; i++) {
            int t = tid + i * 256;
            int r = t >> 4, c8 = (t & 15) * 8;
            const size_t g = (size_t)(k0 + r) * N + colBase + c8;
            cp16(Bs(0, s) + r * GB_ROW + c8, Bh_ + g);
            cp16(Bs(1, s) + r * GB_ROW + c8, Bl_ + g);
        }
        asm volatile("cp.async.commit_group;\n" ::: "memory");
    };

    issue(0);
    issue(1);
    for (int c = 0; c < nc; c++) {
        const int s = c % 3;
        if (c + 2 < nc) {
            asm volatile("cp.async.wait_group 1;\n" ::: "memory");
        } else {
            asm volatile("cp.async.wait_group 0;\n" ::: "memory");
        }
        __syncthreads();
        if (c + 2 < nc) issue(c + 2);

#pragma unroll
        for (int ks = 0; ks < 32; ks += 16) {
            uint32_t ahf[2][4], alf[2][4];
#pragma unroll
            for (int fm = 0; fm < 2; fm++) {
                int row = wm * 32 + fm * 16 + (lane & 15);
                int col = ks + ((lane >> 4) << 3);
                ldsm_x4(ahf[fm], As(0, s) + row * GA_ROW + col);
                ldsm_x4(alf[fm], As(1, s) + row * GA_ROW + col);
            }
            const int brow = ks + (lane & 7) + ((lane >> 3) & 1) * 8;
            const int bcof = (lane >> 4) * 8;
#pragma unroll
            for (int fnp = 0; fnp < 4; fnp++) {
                const int bcol = wn * 64 + fnp * 16 + bcof;
                uint32_t bh4[4];
                ldsm_x4t(bh4, Bs(0, s) + brow * GB_ROW + bcol);
#pragma unroll
                for (int fm = 0; fm < 2; fm++) {
                    mma_16816(acc[fm][2 * fnp],     ahf[fm], bh4 + 0);
                    mma_16816(acc[fm][2 * fnp + 1], ahf[fm], bh4 + 2);
                }
#pragma unroll
                for (int fm = 0; fm < 2; fm++) {
                    mma_16816(acc[fm][2 * fnp],     alf[fm], bh4 + 0);
                    mma_16816(acc[fm][2 * fnp + 1], alf[fm], bh4 + 2);
                }
                uint32_t bl4[4];
                ldsm_x4t(bl4, Bs(1, s) + brow * GB_ROW + bcol);
#pragma unroll
                for (int fm = 0; fm < 2; fm++) {
                    mma_16816(acc[fm][2 * fnp],     ahf[fm], bl4 + 0);
                    mma_16816(acc[fm][2 * fnp + 1], ahf[fm], bl4 + 2);
                }
            }
        }
        __syncthreads();
    }

#pragma unroll
    for (int fm = 0; fm < 2; fm++) {
#pragma unroll
        for (int fn = 0; fn < 8; fn++) {
            int r0 = rowBase + wm * 32 + fm * 16 + (lane >> 2);
            int c0 = colBase + wn * 64 + fn * 8 + (lane & 3) * 2;
            float bx = 0.f, by = 0.f;
            if (BIAS) { bx = bias[c0]; by = bias[c0 + 1]; }
#pragma unroll
            for (int hh = 0; hh < 2; hh++) {
                int r = r0 + hh * 8;
                float v0 = acc[fm][fn][hh * 2 + 0] + bx;
                float v1 = acc[fm][fn][hh * 2 + 1] + by;
                if (RELU) { v0 = fmaxf(v0, 0.f); v1 = fmaxf(v1, 0.f); }
                size_t idx = (size_t)r * N + c0;
                if (SPLIT) {
                    __nv_bfloat16 h0 = __float2bfloat16(v0);
                    __nv_bfloat16 h1 = __float2bfloat16(v1);
                    __nv_bfloat162 hp; hp.x = h0; hp.y = h1;
                    *reinterpret_cast<__nv_bfloat162*>(&Ch[idx]) = hp;
                    __nv_bfloat162 lp;
                    lp.x = __float2bfloat16(v0 - __bfloat162float(h0));
                    lp.y = __float2bfloat16(v1 - __bfloat162float(h1));
                    *reinterpret_cast<__nv_bfloat162*>(&Cl[idx]) = lp;
                } else {
                    if (resid != nullptr) {
                        float2 rv = *reinterpret_cast<const float2*>(&resid[idx]);
                        v0 += rv.x;
                        v1 += rv.y;
                    }
                    *reinterpret_cast<float2*>(&C[idx]) = make_float2(v0, v1);
                }
            }
        }
    }
}

// ---------------------------------------------------------------------------
// Attention (best/R13 config): Br=64, 128 threads, single-stage K/V.
// ---------------------------------------------------------------------------
#define APAD 72
#define ATILE (64 * APAD)
#define ATT_SMEM_BYTES (6 * ATILE * 2 + 64 * 4)

__global__ __launch_bounds__(128) void attn_mma(
    const __nv_bfloat16* __restrict__ Qh, const __nv_bfloat16* __restrict__ Ql,
    const __nv_bfloat16* __restrict__ Kh, const __nv_bfloat16* __restrict__ Kl,
    const __nv_bfloat16* __restrict__ Vh, const __nv_bfloat16* __restrict__ Vl,
    const int* __restrict__ mask,
    __nv_bfloat16* __restrict__ Oh, __nv_bfloat16* __restrict__ Ol, int ldin)
{
    extern __shared__ __align__(16) __nv_bfloat16 smb[];
    __nv_bfloat16* sQh = smb;
    __nv_bfloat16* sQl = smb + ATILE;
    __nv_bfloat16* sKh = smb + 2 * ATILE;
    __nv_bfloat16* sKl = smb + 3 * ATILE;
    __nv_bfloat16* sVh = smb + 4 * ATILE;
    __nv_bfloat16* sVl = smb + 5 * ATILE;
    int* Ms = (int*)(smb + 6 * ATILE);

    const int qt = blockIdx.x, h = blockIdx.y, b = blockIdx.z;
    const int tid = threadIdx.x, lane = tid & 31, warp = tid >> 5, l16 = lane & 15;
    const size_t rowbase = (size_t)b * S_LEN + qt * 64;
    const int ch = h * DK;

    for (int i = tid; i < 512; i += 128) {
        int r = i >> 3, c8 = (i & 7) * 8;
        size_t g = (rowbase + r) * (size_t)ldin + ch + c8;
        cp16(&sQh[r * APAD + c8], Qh + g);
        cp16(&sQl[r * APAD + c8], Ql + g);
    }
    asm volatile("cp.async.commit_group;\n" ::: "memory");
    asm volatile("cp.async.wait_group 0;\n" ::: "memory");
    __syncthreads();

    uint32_t qfh[4][4], qfl[4][4];
#pragma unroll
    for (int kc = 0; kc < 4; kc++) {
        int row = warp * 16 + l16, col = kc * 16 + (lane >> 4) * 8;
        ldsm_x4(qfh[kc], &sQh[row * APAD + col]);
        ldsm_x4(qfl[kc], &sQl[row * APAD + col]);
    }

    float m0 = -1e30f, m1 = -1e30f, l0 = 0.f, l1 = 0.f;
    float o[8][4];
#pragma unroll
    for (int nf = 0; nf < 8; nf++)
#pragma unroll
        for (int j = 0; j < 4; j++) o[nf][j] = 0.f;

    for (int kt = 0; kt < S_LEN / 64; kt++) {
        __syncthreads();
        for (int i = tid; i < 512; i += 128) {
            int r = i >> 3, c8 = (i & 7) * 8;
            size_t g = ((size_t)b * S_LEN + kt * 64 + r) * (size_t)ldin + ch + c8;
            int so = r * APAD + c8;
            cp16(&sKh[so], Kh + g);
            cp16(&sKl[so], Kl + g);
            cp16(&sVh[so], Vh + g);
            cp16(&sVl[so], Vl + g);
        }
        if (tid < 64) Ms[tid] = mask[(size_t)b * S_LEN + kt * 64 + tid];
        asm volatile("cp.async.commit_group;\n" ::: "memory");
        asm volatile("cp.async.wait_group 0;\n" ::: "memory");
        __syncthreads();

        float s[8][4];
#pragma unroll
        for (int nf = 0; nf < 8; nf++)
#pragma unroll
            for (int j = 0; j < 4; j++) s[nf][j] = 0.f;

#pragma unroll
        for (int kc = 0; kc < 4; kc++) {
            int rr = (l16 & 7), cc = kc * 16 + (l16 >> 3) * 8;
#pragma unroll
            for (int nf = 0; nf < 8; nf++) {
                uint32_t bh[2];
                ldsm_x2(bh, &sKh[(nf * 8 + rr) * APAD + cc]);
                mma_16816(s[nf], qfh[kc], bh);
                mma_16816(s[nf], qfl[kc], bh);
            }
#pragma unroll
            for (int nf = 0; nf < 8; nf++) {
                uint32_t bl[2];
                ldsm_x2(bl, &sKl[(nf * 8 + rr) * APAD + cc]);
                mma_16816(s[nf], qfh[kc], bl);
            }
        }

#pragma unroll
        for (int nf = 0; nf < 8; nf++) {
            int c0 = nf * 8 + (lane & 3) * 2;
            bool z0 = (Ms[c0] == 0), z1 = (Ms[c0 + 1] == 0);
            s[nf][0] = z0 ? -1e9f : s[nf][0] * 0.125f;
            s[nf][1] = z1 ? -1e9f : s[nf][1] * 0.125f;
            s[nf][2] = z0 ? -1e9f : s[nf][2] * 0.125f;
            s[nf][3] = z1 ? -1e9f : s[nf][3] * 0.125f;
        }

        float tm0 = -1e30f, tm1 = -1e30f;
#pragma unroll
        for (int nf = 0; nf < 8; nf++) {
            tm0 = fmaxf(tm0, fmaxf(s[nf][0], s[nf][1]));
            tm1 = fmaxf(tm1, fmaxf(s[nf][2], s[nf][3]));
        }
        tm0 = fmaxf(tm0, __shfl_xor_sync(0xffffffffu, tm0, 1));
        tm0 = fmaxf(tm0, __shfl_xor_sync(0xffffffffu, tm0, 2));
        tm1 = fmaxf(tm1, __shfl_xor_sync(0xffffffffu, tm1, 1));
        tm1 = fmaxf(tm1, __shfl_xor_sync(0xffffffffu, tm1, 2));

        float mn0 = fmaxf(m0, tm0), mn1 = fmaxf(m1, tm1);
        float sc0 = __expf(m0 - mn0), sc1 = __expf(m1 - mn1);
        m0 = mn0; m1 = mn1;

        float ts0 = 0.f, ts1 = 0.f;
#pragma unroll
        for (int nf = 0; nf < 8; nf++) {
            s[nf][0] = __expf(s[nf][0] - m0);
            s[nf][1] = __expf(s[nf][1] - m0);
            s[nf][2] = __expf(s[nf][2] - m1);
            s[nf][3] = __expf(s[nf][3] - m1);
            ts0 += s[nf][0] + s[nf][1];
            ts1 += s[nf][2] + s[nf][3];
        }
        ts0 += __shfl_xor_sync(0xffffffffu, ts0, 1);
        ts0 += __shfl_xor_sync(0xffffffffu, ts0, 2);
        ts1 += __shfl_xor_sync(0xffffffffu, ts1, 1);
        ts1 += __shfl_xor_sync(0xffffffffu, ts1, 2);
        l0 = l0 * sc0 + ts0;
        l1 = l1 * sc1 + ts1;

#pragma unroll
        for (int nf = 0; nf < 8; nf++) {
            o[nf][0] *= sc0; o[nf][1] *= sc0;
            o[nf][2] *= sc1; o[nf][3] *= sc1;
        }

#pragma unroll
        for (int j = 0; j < 4; j++) {
            uint32_t ah[4], al[4];
#pragma unroll
            for (int half = 0; half < 2; half++) {
                const float* p = s[2 * j + half];
#pragma unroll
                for (int rr2 = 0; rr2 < 2; rr2++) {
                    float p0 = p[rr2 * 2 + 0], p1 = p[rr2 * 2 + 1];
                    __nv_bfloat16 h0 = __float2bfloat16(p0), h1 = __float2bfloat16(p1);
                    __nv_bfloat162 hp; hp.x = h0; hp.y = h1;
                    ah[half * 2 + rr2] = *reinterpret_cast<uint32_t*>(&hp);
                    al[half * 2 + rr2] = pack_bf16(p0 - __bfloat162float(h0),
                                                   p1 - __bfloat162float(h1));
                }
            }
            int vrow = j * 16 + l16;
#pragma unroll
            for (int nf = 0; nf < 8; nf++) {
                uint32_t bvh[2];
                ldsm_x2t(bvh, &sVh[vrow * APAD + nf * 8]);
                mma_16816(o[nf], ah, bvh);
                mma_16816(o[nf], al, bvh);
            }
#pragma unroll
            for (int nf = 0; nf < 8; nf++) {
                uint32_t bvl[2];
                ldsm_x2t(bvl, &sVl[vrow * APAD + nf * 8]);
                mma_16816(o[nf], ah, bvl);
            }
        }
    }

    float inv0 = 1.f / l0, inv1 = 1.f / l1;
    int r0 = warp * 16 + (lane >> 2);
#pragma unroll
    for (int nf = 0; nf < 8; nf++) {
        int c0 = ch + nf * 8 + (lane & 3) * 2;
#pragma unroll
        for (int hh = 0; hh < 2; hh++) {
            float v0 = o[nf][hh * 2 + 0] * (hh ? inv1 : inv0);
            float v1 = o[nf][hh * 2 + 1] * (hh ? inv1 : inv0);
            size_t idx = (rowbase + r0 + hh * 8) * D_MODEL + c0;
            __nv_bfloat16 h0 = __float2bfloat16(v0), h1 = __float2bfloat16(v1);
            __nv_bfloat162 hp; hp.x = h0; hp.y = h1;
            *reinterpret_cast<__nv_bfloat162*>(&Oh[idx]) = hp;
            __nv_bfloat162 lp;
            lp.x = __float2bfloat16(v0 - __bfloat162float(h0));
            lp.y = __float2bfloat16(v1 - __bfloat162float(h1));
            *reinterpret_cast<__nv_bfloat162*>(&Ol[idx]) = lp;
        }
    }
}

// ---------------- LayerNorm over a pre-summed buffer ----------------
template <bool SPLITOUT>
__global__ __launch_bounds__(256) void ln_kernel(
    const float* __restrict__ A,
    const float* __restrict__ alpha, const float* __restrict__ beta,
    float* __restrict__ out, __nv_bfloat16* __restrict__ oh,
    __nv_bfloat16* __restrict__ ol)
{
    __shared__ float buf[D_MODEL];
    __shared__ float red_s[8], red_q[8];
    __shared__ float sh_mean, sh_inv;
    const int row = blockIdx.x, tid = threadIdx.x;
    const size_t base = (size_t)row * D_MODEL;

    float s = 0.f, q = 0.f;
    for (int c = tid; c < D_MODEL; c += 256) {
        float v = A[base + c];
        buf[c] = v; s += v; q = fmaf(v, v, q);
    }
#pragma unroll
    for (int msk = 16; msk >= 1; msk >>= 1) {
        s += __shfl_xor_sync(0xffffffffu, s, msk);
        q += __shfl_xor_sync(0xffffffffu, q, msk);
    }
    if ((tid & 31) == 0) { red_s[tid >> 5] = s; red_q[tid >> 5] = q; }
    __syncthreads();
    if (tid == 0) {
        float S = 0.f, Q = 0.f;
#pragma unroll
        for (int i = 0; i < 8; i++) { S += red_s[i]; Q += red_q[i]; }
        float mean = S * (1.f / (float)D_MODEL);
        float var = fmaxf((Q - (float)D_MODEL * mean * mean) *
                          (1.f / (float)(D_MODEL - 1)), 0.f);
        sh_mean = mean;
        sh_inv = 1.f / (sqrtf(var) + 1e-6f);
    }
    __syncthreads();
    const float mean = sh_mean, inv = sh_inv;
    for (int c = tid; c < D_MODEL; c += 256) {
        float v = fmaf(alpha[c], (buf[c] - mean) * inv, beta[c]);
        out[base + c] = v;
        if (SPLITOUT) {
            __nv_bfloat16 hv = __float2bfloat16(v);
            oh[base + c] = hv;
            ol[base + c] = __float2bfloat16(v - __bfloat162float(hv));
        }
    }
}

// ---------------- launch (dual-stream overlap) ----------------
extern "C" void kernel_launch(void* const* d_in, const int* in_sizes, int n_in,
                              void* d_out, int out_size)
{
    const float* x   = (const float*)d_in[0];
    const int* mask  = (const int*)d_in[1];
    const float* w_q = (const float*)d_in[2];
    const float* w_k = (const float*)d_in[3];
    const float* w_v = (const float*)d_in[4];
    const float* w_o = (const float*)d_in[5];
    const float* W1  = (const float*)d_in[6];
    const float* b1  = (const float*)d_in[7];
    const float* W2  = (const float*)d_in[8];
    const float* b2  = (const float*)d_in[9];
    const float* a1  = (const float*)d_in[10];
    const float* be1 = (const float*)d_in[11];
    const float* a2  = (const float*)d_in[12];
    const float* be2 = (const float*)d_in[13];
    float* out = (float*)d_out;

    float *O, *X1;
    cudaGetSymbolAddress((void**)&O, g_O);
    cudaGetSymbolAddress((void**)&X1, g_X1);
    __nv_bfloat16 *xh, *xl, *qkvh, *qkvl, *wqkvh, *wqkvl, *woh, *wol;
    __nv_bfloat16 *W1h, *W1l, *W2h, *W2l, *aoh, *aol, *x1h, *x1l, *Hh, *Hl;
    cudaGetSymbolAddress((void**)&xh, g_xh);       cudaGetSymbolAddress((void**)&xl, g_xl);
    cudaGetSymbolAddress((void**)&qkvh, g_qkvh);   cudaGetSymbolAddress((void**)&qkvl, g_qkvl);
    cudaGetSymbolAddress((void**)&wqkvh, g_wqkvh); cudaGetSymbolAddress((void**)&wqkvl, g_wqkvl);
    cudaGetSymbolAddress((void**)&woh, g_woh);     cudaGetSymbolAddress((void**)&wol, g_wol);
    cudaGetSymbolAddress((void**)&W1h, g_W1h);     cudaGetSymbolAddress((void**)&W1l, g_W1l);
    cudaGetSymbolAddress((void**)&W2h, g_W2h);     cudaGetSymbolAddress((void**)&W2l, g_W2l);
    cudaGetSymbolAddress((void**)&aoh, g_aoh);     cudaGetSymbolAddress((void**)&aol, g_aol);
    cudaGetSymbolAddress((void**)&x1h, g_x1h);     cudaGetSymbolAddress((void**)&x1l, g_x1l);
    cudaGetSymbolAddress((void**)&Hh, g_Hh);       cudaGetSymbolAddress((void**)&Hl, g_Hl);

    cudaFuncSetAttribute(attn_mma, cudaFuncAttributeMaxDynamicSharedMemorySize,
                         ATT_SMEM_BYTES);
    cudaFuncSetAttribute(hgemm_fused<false, false, true>,
                         cudaFuncAttributeMaxDynamicSharedMemorySize, GSMEM_TOTAL);
    cudaFuncSetAttribute(hgemm_fused<false, false, false>,
                         cudaFuncAttributeMaxDynamicSharedMemorySize, GSMEM_TOTAL);
    cudaFuncSetAttribute(hgemm_fused<true, true, true>,
                         cudaFuncAttributeMaxDynamicSharedMemorySize, GSMEM_TOTAL);
    cudaFuncSetAttribute(hgemm_fused<true, false, false>,
                         cudaFuncAttributeMaxDynamicSharedMemorySize, GSMEM_TOTAL);

    // Side stream + fork/join events (host objects; created per call, leaked —
    // kernel_launch runs only for correctness + capture, never per-replay).
    cudaStream_t s2;
    cudaStreamCreate(&s2);
    cudaEvent_t eF1, eJ1, eF2, eJ2;
    cudaEventCreateWithFlags(&eF1, cudaEventDisableTiming);
    cudaEventCreateWithFlags(&eJ1, cudaEventDisableTiming);
    cudaEventCreateWithFlags(&eF2, cudaEventDisableTiming);
    cudaEventCreateWithFlags(&eJ2, cudaEventDisableTiming);

    const dim3 blk(256);
    const dim3 gQKV(D3 / 128, ROWS / 128);
    const dim3 gP(D_MODEL / 128, ROWS / 128);
    const dim3 gF(DFF / 128, ROWS / 128);

    // ---- fork 1: x split (main) || qkv weight split (s2) ----
    cudaEventRecord(eF1, 0);
    cudaStreamWaitEvent(s2, eF1, 0);
    split_qkv_kernel<<<dim3(MM / 1024, 1, 3), blk, 0, s2>>>(
        (const float4*)w_q, (const float4*)w_k, (const float4*)w_v, wqkvh, wqkvl);
    split4_kernel<<<RM / 4096, blk>>>((const float4*)x, xh, xl, RM / 4);
    cudaEventRecord(eJ1, s2);
    cudaStreamWaitEvent(0, eJ1, 0);

    hgemm_fused<false, false, true><<<gQKV, blk, GSMEM_TOTAL>>>(
        xh, xl, wqkvh, wqkvl, nullptr, nullptr, nullptr, qkvh, qkvl,
        ROWS, D3, D_MODEL);

    // ---- fork 2: attention (main) || w_o/W1/W2 splits (s2) ----
    cudaEventRecord(eF2, 0);
    cudaStreamWaitEvent(s2, eF2, 0);
    attn_mma<<<dim3(S_LEN / 64, HEADS, BATCH), 128, ATT_SMEM_BYTES>>>(
        qkvh, qkvl, qkvh + D_MODEL, qkvl + D_MODEL,
        qkvh + 2 * D_MODEL, qkvl + 2 * D_MODEL, mask, aoh, aol, D3);
    split4_kernel<<<MM / 4096, blk, 0, s2>>>((const float4*)w_o, woh, wol, MM / 4);
    split4_kernel<<<MF / 4096, blk, 0, s2>>>((const float4*)W1, W1h, W1l, MF / 4);
    split4_kernel<<<MF / 4096, blk, 0, s2>>>((const float4*)W2, W2h, W2l, MF / 4);
    cudaEventRecord(eJ2, s2);
    cudaStreamWaitEvent(0, eJ2, 0);

    // o-proj with fused residual (+x) -> O holds x + attn@w_o
    hgemm_fused<false, false, false><<<gP, blk, GSMEM_TOTAL>>>(
        aoh, aol, woh, wol, nullptr, x, O, nullptr, nullptr,
        ROWS, D_MODEL, D_MODEL);

    ln_kernel<true><<<ROWS, blk>>>(O, a1, be1, X1, x1h, x1l);

    hgemm_fused<true, true, true><<<gF, blk, GSMEM_TOTAL>>>(
        x1h, x1l, W1h, W1l, b1, nullptr, nullptr, Hh, Hl, ROWS, DFF, D_MODEL);

    // FFN2 with fused residual (+X1) -> O holds X1 + ffn_out
    hgemm_fused<true, false, false><<<gP, blk, GSMEM_TOTAL>>>(
        Hh, Hl, W2h, W2l, b2, X1, O, nullptr, nullptr, ROWS, D_MODEL, DFF);

    ln_kernel<false><<<ROWS, blk>>>(O, a2, be2, out, nullptr, nullptr);
}